// round 2
// baseline (speedup 1.0000x reference)
#include <cuda_runtime.h>

#define MAXN 50000
#define MAXE 800000
#define CH 96          // padded feature channels (88 real: 4 x + 84 edge_attr)
#define OC 128
#define OUTC 64
#define EPSV 1e-5f

// ---------------- device scratch (static globals: no allocs allowed) -------
__device__ int   g_is64;
__device__ int   g_row[MAXE];
__device__ int   g_col[MAXE];
__device__ int   g_cnt[MAXN];
__device__ int   g_off[MAXN + 1];
__device__ int   g_cur[MAXN];
__device__ int   g_perm[MAXE];
__device__ float g_S[(size_t)MAXN * CH];   // per-node summed features
__device__ float g_M[CH * CH];             // second-moment matrix sum f f^T
__device__ float g_sv[CH];                 // global feature sum s
__device__ float g_mean[OC];
__device__ float g_scale[OC];              // gamma * rsqrt(var+eps)

// ---------------- dtype detection: int64 vs int32 edge_index ----------------
// Genuine int64 indices are all in [0, MAXN). int32 data reinterpreted as
// int64 packs two values -> magnitudes >= 2^32 almost surely within 64 samples.
__global__ void k_detect(const void* ei) {
    const long long* p = (const long long*)ei;
    int bad = 0;
    for (int i = threadIdx.x; i < 64; i += 32) {
        long long v = p[i];
        if (v < 0 || v >= MAXN) bad = 1;
    }
    unsigned m = __ballot_sync(0xffffffffu, bad);
    if (threadIdx.x == 0) g_is64 = (m == 0) ? 1 : 0;
}

__global__ void k_convert(const void* ei, int E) {
    int is64 = g_is64;
    int i = blockIdx.x * blockDim.x + threadIdx.x;
    int T = gridDim.x * blockDim.x;
    if (is64) {
        const long long* p = (const long long*)ei;
        for (int e = i; e < E; e += T) { g_row[e] = (int)p[e]; g_col[e] = (int)p[E + e]; }
    } else {
        const int* p = (const int*)ei;
        for (int e = i; e < E; e += T) { g_row[e] = p[e]; g_col[e] = p[E + e]; }
    }
}

// ---------------- zero scratch ---------------------------------------------
__global__ void k_zero(int N) {
    int i = blockIdx.x * blockDim.x + threadIdx.x;
    int T = gridDim.x * blockDim.x;
    for (int j = i; j < N; j += T) g_cnt[j] = 0;
    for (int j = i; j < CH * CH; j += T) g_M[j] = 0.f;
    if (i < CH) g_sv[i] = 0.f;
}

// ---------------- histogram of row (target node) ---------------------------
__global__ void k_hist(int E) {
    int i = blockIdx.x * blockDim.x + threadIdx.x;
    int T = gridDim.x * blockDim.x;
    for (int e = i; e < E; e += T) atomicAdd(&g_cnt[g_row[e]], 1);
}

// ---------------- exclusive scan (single CTA) ------------------------------
__global__ void k_scan(int N, int E) {
    __shared__ int part[1024];
    int tid = threadIdx.x;
    int chunk = (N + 1023) >> 10;
    int beg = tid * chunk;
    int end = min(beg + chunk, N);
    int s = 0;
    for (int i = beg; i < end; i++) s += g_cnt[i];
    part[tid] = s;
    __syncthreads();
    if (tid == 0) {
        int r = 0;
        for (int i = 0; i < 1024; i++) { int t = part[i]; part[i] = r; r += t; }
        g_off[N] = E;
    }
    __syncthreads();
    int r = part[tid];
    for (int i = beg; i < end; i++) { g_off[i] = r; g_cur[i] = r; r += g_cnt[i]; }
}

// ---------------- build CSR permutation ------------------------------------
__global__ void k_perm(int E) {
    int i = blockIdx.x * blockDim.x + threadIdx.x;
    int T = gridDim.x * blockDim.x;
    for (int e = i; e < E; e += T) {
        int r = g_row[e];
        int p = atomicAdd(&g_cur[r], 1);
        g_perm[p] = e;
    }
}

// ---------------- per-node feature sum (gather, no atomics) ----------------
// warp per node; lane l accumulates channels l, 32+l, 64+l.
__global__ void k_agg(const float* __restrict__ x, const float* __restrict__ ea,
                      int N) {
    int lane = threadIdx.x & 31;
    int warp = (blockIdx.x * blockDim.x + threadIdx.x) >> 5;
    int nw = (gridDim.x * blockDim.x) >> 5;
    for (int n = warp; n < N; n += nw) {
        int beg = g_off[n], end = g_off[n + 1];
        float a0 = 0.f, a1 = 0.f, a2 = 0.f;
        for (int j = beg; j < end; j++) {
            int e = g_perm[j];
            const float* fe = ea + (size_t)e * 84;
            float v0;
            if (lane < 4) { int col = g_col[e]; v0 = x[col * 4 + lane]; }
            else          { v0 = fe[lane - 4]; }
            a0 += v0;
            a1 += fe[28 + lane];
            if (lane < 24) a2 += fe[60 + lane];
        }
        float* so = g_S + (size_t)n * CH;
        so[lane] = a0;
        so[32 + lane] = a1;
        so[64 + lane] = (lane < 24) ? a2 : 0.f;
    }
}

// ---------------- M = sum_e f f^T  (96x96 SYRK, K=E) -----------------------
#define KB 64
#define ROWL 70   // padded k-row length (bank-conflict friendly)

__device__ __forceinline__ void fma2(unsigned long long& d,
                                     unsigned long long a, unsigned long long b) {
    asm("fma.rn.f32x2 %0, %1, %2, %0;" : "+l"(d) : "l"(a), "l"(b));
}

__global__ void __launch_bounds__(256, 2)
k_M(const float* __restrict__ x, const float* __restrict__ ea, int E) {
    __shared__ float tile[CH * ROWL];   // [channel][k] , k contiguous
    int tid = threadIdx.x;
    int lane = tid & 31, w = tid >> 5;
    int tx = tid & 15, ty = tid >> 4;
    unsigned long long acc[6][6];
#pragma unroll
    for (int i = 0; i < 6; i++)
#pragma unroll
        for (int j = 0; j < 6; j++) acc[i][j] = 0ull;
    float s0 = 0.f, s1 = 0.f, s2 = 0.f;
    int nchunk = (E + KB - 1) / KB;
    for (int c = blockIdx.x; c < nchunk; c += gridDim.x) {
        long long base = (long long)c * KB;
        // load + transpose chunk into smem (channel-major, k contiguous)
        for (int ee = w; ee < KB; ee += 8) {
            long long e = base + ee;
            float v0 = 0.f, v1 = 0.f, v2 = 0.f;
            if (e < E) {
                const float* fe = ea + e * 84;
                if (lane < 4) { int col = g_col[e]; v0 = x[col * 4 + lane]; }
                else          { v0 = fe[lane - 4]; }
                v1 = fe[28 + lane];
                if (lane < 24) v2 = fe[60 + lane];
            }
            tile[lane * ROWL + ee] = v0;
            tile[(32 + lane) * ROWL + ee] = v1;
            tile[(64 + lane) * ROWL + ee] = v2;
            s0 += v0; s1 += v1; s2 += v2;
        }
        __syncthreads();
#pragma unroll 8
        for (int kk = 0; kk < KB / 2; kk++) {
            unsigned long long a[6], b[6];
#pragma unroll
            for (int i = 0; i < 6; i++)
                a[i] = *(const unsigned long long*)&tile[(ty * 6 + i) * ROWL + 2 * kk];
#pragma unroll
            for (int j = 0; j < 6; j++)
                b[j] = *(const unsigned long long*)&tile[(tx * 6 + j) * ROWL + 2 * kk];
#pragma unroll
            for (int i = 0; i < 6; i++)
#pragma unroll
                for (int j = 0; j < 6; j++) fma2(acc[i][j], a[i], b[j]);
        }
        __syncthreads();
    }
#pragma unroll
    for (int i = 0; i < 6; i++)
#pragma unroll
        for (int j = 0; j < 6; j++) {
            float2 v = *(float2*)&acc[i][j];
            atomicAdd(&g_M[(ty * 6 + i) * CH + tx * 6 + j], v.x + v.y);
        }
    atomicAdd(&g_sv[lane], s0);
    atomicAdd(&g_sv[32 + lane], s1);
    if (lane < 24) atomicAdd(&g_sv[64 + lane], s2);
}

// ---------------- BN stats: mean/scale per output channel ------------------
// sum_e h_c = s.w_c + E*b1_c ; sum_e h_c^2 = w_c^T M w_c + 2 b1_c (s.w_c) + E b1_c^2
__global__ void k_bn(const float* __restrict__ W1, const float* __restrict__ b1,
                     const float* __restrict__ gamma, float fE) {
    int c = blockIdx.x;
    int t = threadIdx.x;  // 96 threads
    __shared__ float w[CH];
    __shared__ float rq[CH];
    __shared__ float rs[CH];
    w[t] = (t < 88) ? W1[t * OC + c] : 0.f;
    __syncthreads();
    float q = 0.f;
    if (t < 88) {
        const float* Mr = g_M + t * CH;
        for (int k = 0; k < 88; k++) q += Mr[k] * w[k];
        q *= w[t];
    }
    rq[t] = q;
    rs[t] = (t < 88) ? g_sv[t] * w[t] : 0.f;
    __syncthreads();
    if (t == 0) {
        float Q = 0.f, SW = 0.f;
        for (int i = 0; i < 88; i++) { Q += rq[i]; SW += rs[i]; }
        float b = b1[c];
        float mean = SW / fE + b;
        float ex2 = (Q + 2.f * b * SW) / fE + b * b;
        float var = ex2 - mean * mean;
        g_mean[c] = mean;
        g_scale[c] = gamma[c] * rsqrtf(var + EPSV);
    }
}

// ---------------- node output: agg = BN(S/cnt @ W1 + b1); out = relu([x,agg]@W2+b2)
__global__ void k_out(const float* __restrict__ x, const float* __restrict__ W1,
                      const float* __restrict__ b1, const float* __restrict__ beta,
                      const float* __restrict__ W2, const float* __restrict__ b2,
                      float* __restrict__ out, int N) {
    extern __shared__ float sm[];
    float* W1s = sm;             // 88*128
    float* W2s = sm + 88 * OC;   // 132*64
    int tid = threadIdx.x;
    for (int i = tid; i < 88 * OC; i += blockDim.x) W1s[i] = W1[i];
    for (int i = tid; i < 132 * OUTC; i += blockDim.x) W2s[i] = W2[i];
    __syncthreads();
    int lane = tid & 31;
    int warp = (blockIdx.x * blockDim.x + tid) >> 5;
    int nw = (gridDim.x * blockDim.x) >> 5;
    float mn0 = g_mean[lane], mn1 = g_mean[32 + lane], mn2 = g_mean[64 + lane], mn3 = g_mean[96 + lane];
    float sc0 = g_scale[lane], sc1 = g_scale[32 + lane], sc2 = g_scale[64 + lane], sc3 = g_scale[96 + lane];
    float bt0 = beta[lane], bt1 = beta[32 + lane], bt2 = beta[64 + lane], bt3 = beta[96 + lane];
    float bo0 = b1[lane], bo1 = b1[32 + lane], bo2 = b1[64 + lane], bo3 = b1[96 + lane];
    float bb0 = b2[lane], bb1 = b2[32 + lane];
    for (int n = warp; n < N; n += nw) {
        const float* so = g_S + (size_t)n * CH;
        float sr0 = so[lane], sr1 = so[32 + lane], sr2 = so[64 + lane];
        int cnt = g_off[n + 1] - g_off[n];
        float acc0 = 0.f, acc1 = 0.f, acc2 = 0.f, acc3 = 0.f;
#pragma unroll
        for (int cc = 0; cc < 32; cc++) {
            float v = __shfl_sync(0xffffffffu, sr0, cc);
            const float* wr = W1s + cc * OC + lane;
            acc0 += v * wr[0]; acc1 += v * wr[32]; acc2 += v * wr[64]; acc3 += v * wr[96];
        }
#pragma unroll
        for (int cc = 0; cc < 32; cc++) {
            float v = __shfl_sync(0xffffffffu, sr1, cc);
            const float* wr = W1s + (32 + cc) * OC + lane;
            acc0 += v * wr[0]; acc1 += v * wr[32]; acc2 += v * wr[64]; acc3 += v * wr[96];
        }
#pragma unroll
        for (int cc = 0; cc < 24; cc++) {
            float v = __shfl_sync(0xffffffffu, sr2, cc);
            const float* wr = W1s + (64 + cc) * OC + lane;
            acc0 += v * wr[0]; acc1 += v * wr[32]; acc2 += v * wr[64]; acc3 += v * wr[96];
        }
        float t = (cnt > 0) ? 1.f : 0.f;
        float r = (cnt > 0) ? 1.f / (float)cnt : 0.f;
        float ag0 = ((acc0 * r + bo0 - mn0) * sc0 + bt0) * t;
        float ag1 = ((acc1 * r + bo1 - mn1) * sc1 + bt1) * t;
        float ag2 = ((acc2 * r + bo2 - mn2) * sc2 + bt2) * t;
        float ag3 = ((acc3 * r + bo3 - mn3) * sc3 + bt3) * t;
        float o0 = bb0, o1 = bb1;
        const float* xr = x + (size_t)n * 4;
#pragma unroll
        for (int k = 0; k < 4; k++) {
            float xv = xr[k];
            o0 += xv * W2s[k * OUTC + lane];
            o1 += xv * W2s[k * OUTC + 32 + lane];
        }
#pragma unroll
        for (int cc = 0; cc < 32; cc++) {
            float av = __shfl_sync(0xffffffffu, ag0, cc);
            const float* wr = W2s + (4 + cc) * OUTC + lane;
            o0 += av * wr[0]; o1 += av * wr[32];
        }
#pragma unroll
        for (int cc = 0; cc < 32; cc++) {
            float av = __shfl_sync(0xffffffffu, ag1, cc);
            const float* wr = W2s + (36 + cc) * OUTC + lane;
            o0 += av * wr[0]; o1 += av * wr[32];
        }
#pragma unroll
        for (int cc = 0; cc < 32; cc++) {
            float av = __shfl_sync(0xffffffffu, ag2, cc);
            const float* wr = W2s + (68 + cc) * OUTC + lane;
            o0 += av * wr[0]; o1 += av * wr[32];
        }
#pragma unroll
        for (int cc = 0; cc < 32; cc++) {
            float av = __shfl_sync(0xffffffffu, ag3, cc);
            const float* wr = W2s + (100 + cc) * OUTC + lane;
            o0 += av * wr[0]; o1 += av * wr[32];
        }
        out[(size_t)n * 64 + lane] = fmaxf(o0, 0.f);
        out[(size_t)n * 64 + 32 + lane] = fmaxf(o1, 0.f);
    }
}

// ---------------- launcher --------------------------------------------------
extern "C" void kernel_launch(void* const* d_in, const int* in_sizes, int n_in,
                              void* d_out, int out_size) {
    const float* x     = (const float*)d_in[0];
    const void*  ei    = d_in[1];
    const float* ea    = (const float*)d_in[2];
    const float* W1    = (const float*)d_in[3];
    const float* b1    = (const float*)d_in[4];
    const float* gamma = (const float*)d_in[5];
    const float* beta  = (const float*)d_in[6];
    const float* W2    = (const float*)d_in[7];
    const float* b2    = (const float*)d_in[8];
    float* out = (float*)d_out;
    int N = in_sizes[0] / 4;
    int E = in_sizes[2] / 84;

    k_detect<<<1, 32>>>(ei);
    k_convert<<<512, 256>>>(ei, E);
    k_zero<<<128, 256>>>(N);
    k_hist<<<512, 256>>>(E);
    k_scan<<<1, 1024>>>(N, E);
    k_perm<<<512, 256>>>(E);
    k_agg<<<592, 256>>>(x, ea, N);
    k_M<<<296, 256>>>(x, ea, E);
    k_bn<<<128, 96>>>(W1, b1, gamma, (float)E);
    const int smem = (88 * OC + 132 * OUTC) * 4;  // 78848 B
    cudaFuncSetAttribute(k_out, cudaFuncAttributeMaxDynamicSharedMemorySize, smem);
    k_out<<<296, 256, smem>>>(x, W1, b1, beta, W2, b2, out, N);
}

// round 4
// speedup vs baseline: 1.0399x; 1.0399x over previous
#include <cuda_runtime.h>
#include <cuda_bf16.h>
#include <cstdint>

#define MAXN 50000
#define MAXE 800000
#define CH 96          // padded feature channels (88 real: 4 x + 84 edge_attr)
#define OC 128
#define OUTC 64
#define EPSV 1e-5f

// ---------------- device scratch (static globals: no allocs allowed) -------
__device__ int   g_is64;
__device__ int   g_row[MAXE];
__device__ int   g_col[MAXE];
__device__ int   g_cnt[MAXN];
__device__ int   g_off[MAXN + 1];
__device__ int   g_cur[MAXN];
__device__ int   g_perm[MAXE];
__device__ float g_S[(size_t)MAXN * CH];   // per-node summed features
__device__ float g_M[CH * CH];             // second-moment matrix sum f f^T
__device__ float g_sv[CH];                 // global feature sum s
__device__ float g_mean[OC];
__device__ float g_scale[OC];              // gamma * rsqrt(var+eps)

__device__ __forceinline__ uint32_t smem_u32(const void* p) {
    uint32_t a;
    asm("{ .reg .u64 t; cvta.to.shared.u64 t, %1; cvt.u32.u64 %0, t; }" : "=r"(a) : "l"(p));
    return a;
}

// ---------------- dtype detection: int64 vs int32 edge_index ----------------
__global__ void k_detect(const void* ei) {
    const long long* p = (const long long*)ei;
    int bad = 0;
    for (int i = threadIdx.x; i < 64; i += 32) {
        long long v = p[i];
        if (v < 0 || v >= MAXN) bad = 1;
    }
    unsigned m = __ballot_sync(0xffffffffu, bad);
    if (threadIdx.x == 0) g_is64 = (m == 0) ? 1 : 0;
}

__global__ void k_convert(const void* ei, int E) {
    int is64 = g_is64;
    int i = blockIdx.x * blockDim.x + threadIdx.x;
    int T = gridDim.x * blockDim.x;
    if (is64) {
        const long long* p = (const long long*)ei;
        for (int e = i; e < E; e += T) { g_row[e] = (int)p[e]; g_col[e] = (int)p[E + e]; }
    } else {
        const int* p = (const int*)ei;
        for (int e = i; e < E; e += T) { g_row[e] = p[e]; g_col[e] = p[E + e]; }
    }
}

// ---------------- zero scratch ---------------------------------------------
__global__ void k_zero(int N) {
    int i = blockIdx.x * blockDim.x + threadIdx.x;
    int T = gridDim.x * blockDim.x;
    for (int j = i; j < N; j += T) g_cnt[j] = 0;
    for (int j = i; j < CH * CH; j += T) g_M[j] = 0.f;
    if (i < CH) g_sv[i] = 0.f;
}

__global__ void k_hist(int E) {
    int i = blockIdx.x * blockDim.x + threadIdx.x;
    int T = gridDim.x * blockDim.x;
    for (int e = i; e < E; e += T) atomicAdd(&g_cnt[g_row[e]], 1);
}

// ---------------- exclusive scan (single CTA) ------------------------------
__global__ void k_scan(int N, int E) {
    __shared__ int part[1024];
    int tid = threadIdx.x;
    int chunk = (N + 1023) >> 10;
    int beg = tid * chunk;
    int end = min(beg + chunk, N);
    int s = 0;
    for (int i = beg; i < end; i++) s += g_cnt[i];
    part[tid] = s;
    __syncthreads();
    if (tid == 0) {
        int r = 0;
        for (int i = 0; i < 1024; i++) { int t = part[i]; part[i] = r; r += t; }
        g_off[N] = E;
    }
    __syncthreads();
    int r = part[tid];
    for (int i = beg; i < end; i++) { g_off[i] = r; g_cur[i] = r; r += g_cnt[i]; }
}

__global__ void k_perm(int E) {
    int i = blockIdx.x * blockDim.x + threadIdx.x;
    int T = gridDim.x * blockDim.x;
    for (int e = i; e < E; e += T) {
        int r = g_row[e];
        int p = atomicAdd(&g_cur[r], 1);
        g_perm[p] = e;
    }
}

// ---------------- per-node feature sum (gather, no atomics) ----------------
__global__ void k_agg(const float* __restrict__ x, const float* __restrict__ ea,
                      int N) {
    int lane = threadIdx.x & 31;
    int warp = (blockIdx.x * blockDim.x + threadIdx.x) >> 5;
    int nw = (gridDim.x * blockDim.x) >> 5;
    for (int n = warp; n < N; n += nw) {
        int beg = g_off[n], end = g_off[n + 1];
        float a0 = 0.f, a1 = 0.f, a2 = 0.f;
        for (int j = beg; j < end; j++) {
            int e = g_perm[j];
            const float* fe = ea + (size_t)e * 84;
            float v0;
            if (lane < 4) { int col = g_col[e]; v0 = x[col * 4 + lane]; }
            else          { v0 = fe[lane - 4]; }
            a0 += v0;
            a1 += fe[28 + lane];
            if (lane < 24) a2 += fe[60 + lane];
        }
        float* so = g_S + (size_t)n * CH;
        so[lane] = a0;
        so[32 + lane] = a1;
        so[64 + lane] = (lane < 24) ? a2 : 0.f;
    }
}

// ---------------- M = sum_e f f^T via bf16 mma.sync (HMMA) -----------------
// Tile: 96 channels x 64 edges, bf16, row stride 144B (conflict-free ldmatrix).
// Warps 2x4: warp covers 48 rows x 24 cols as 3x3 m16n8k16 tiles.
// fp32 accumulators live in registers across all K-chunks; atomicAdd at end.
#define KB 64
#define ROWB 144

__device__ __forceinline__ void ldm_x4(uint32_t* r, uint32_t a) {
    asm volatile("ldmatrix.sync.aligned.m8n8.x4.shared.b16 {%0,%1,%2,%3}, [%4];"
                 : "=r"(r[0]), "=r"(r[1]), "=r"(r[2]), "=r"(r[3]) : "r"(a));
}
__device__ __forceinline__ void ldm_x2(uint32_t* r, uint32_t a) {
    asm volatile("ldmatrix.sync.aligned.m8n8.x2.shared.b16 {%0,%1}, [%2];"
                 : "=r"(r[0]), "=r"(r[1]) : "r"(a));
}
__device__ __forceinline__ void mma_bf16(float* c, const uint32_t* a, const uint32_t* b) {
    asm volatile("mma.sync.aligned.m16n8k16.row.col.f32.bf16.bf16.f32 "
                 "{%0,%1,%2,%3}, {%4,%5,%6,%7}, {%8,%9}, {%0,%1,%2,%3};"
                 : "+f"(c[0]), "+f"(c[1]), "+f"(c[2]), "+f"(c[3])
                 : "r"(a[0]), "r"(a[1]), "r"(a[2]), "r"(a[3]), "r"(b[0]), "r"(b[1]));
}

__global__ void __launch_bounds__(256, 1)
k_Mmma(const float* __restrict__ x, const float* __restrict__ ea, int E) {
    __shared__ __align__(16) char tile[CH * ROWB];   // 13824 B
    uint32_t tb = smem_u32(tile);
    int tid = threadIdx.x;
    int lane = tid & 31, w = tid >> 5;
    int warp_m = w >> 2, warp_n = w & 3;   // 2 x 4
    int Rm = warp_m * 48;                  // 3 x 16 rows
    int Rn = warp_n * 24;                  // 3 x 8 cols

    float acc[3][3][4];
#pragma unroll
    for (int i = 0; i < 3; i++)
#pragma unroll
        for (int j = 0; j < 3; j++)
#pragma unroll
            for (int q = 0; q < 4; q++) acc[i][j][q] = 0.f;

    float s0 = 0.f, s1 = 0.f, s2 = 0.f;
    int nchunk = (E + KB - 1) / KB;
    for (int c = blockIdx.x; c < nchunk; c += gridDim.x) {
        long long base = (long long)c * KB;
        for (int ee = w; ee < KB; ee += 8) {
            long long e = base + ee;
            float v0 = 0.f, v1 = 0.f, v2 = 0.f;
            if (e < E) {
                const float* fe = ea + e * 84;
                if (lane < 4) { int col = g_col[e]; v0 = x[col * 4 + lane]; }
                else          { v0 = fe[lane - 4]; }
                v1 = fe[28 + lane];
                if (lane < 24) v2 = fe[60 + lane];
            }
            s0 += v0; s1 += v1; s2 += v2;
            *(__nv_bfloat16*)(tile + lane * ROWB + ee * 2) = __float2bfloat16(v0);
            *(__nv_bfloat16*)(tile + (32 + lane) * ROWB + ee * 2) = __float2bfloat16(v1);
            *(__nv_bfloat16*)(tile + (64 + lane) * ROWB + ee * 2) =
                (lane < 24) ? __float2bfloat16(v2) : __nv_bfloat16(0.f);
        }
        __syncthreads();
#pragma unroll
        for (int ks = 0; ks < KB / 16; ks++) {
            uint32_t af[3][4], bf[3][2];
#pragma unroll
            for (int i = 0; i < 3; i++) {
                uint32_t addr = tb + (uint32_t)((Rm + i * 16 + (lane & 15)) * ROWB
                                                + ks * 32 + (lane >> 4) * 16);
                ldm_x4(af[i], addr);
            }
#pragma unroll
            for (int j = 0; j < 3; j++) {
                uint32_t addr = tb + (uint32_t)((Rn + j * 8 + (lane & 7)) * ROWB
                                                + ks * 32 + ((lane >> 3) & 1) * 16);
                ldm_x2(bf[j], addr);
            }
#pragma unroll
            for (int i = 0; i < 3; i++)
#pragma unroll
                for (int j = 0; j < 3; j++) mma_bf16(acc[i][j], af[i], bf[j]);
        }
        __syncthreads();
    }
    // writeback
#pragma unroll
    for (int i = 0; i < 3; i++)
#pragma unroll
        for (int j = 0; j < 3; j++) {
            int row = Rm + i * 16 + (lane >> 2);
            int col = Rn + j * 8 + (lane & 3) * 2;
            atomicAdd(&g_M[row * CH + col], acc[i][j][0]);
            atomicAdd(&g_M[row * CH + col + 1], acc[i][j][1]);
            atomicAdd(&g_M[(row + 8) * CH + col], acc[i][j][2]);
            atomicAdd(&g_M[(row + 8) * CH + col + 1], acc[i][j][3]);
        }
    atomicAdd(&g_sv[lane], s0);
    atomicAdd(&g_sv[32 + lane], s1);
    if (lane < 24) atomicAdd(&g_sv[64 + lane], s2);
}

// ---------------- BN stats --------------------------------------------------
__global__ void k_bn(const float* __restrict__ W1, const float* __restrict__ b1,
                     const float* __restrict__ gamma, float fE) {
    int c = blockIdx.x;
    int t = threadIdx.x;  // 96 threads
    __shared__ float w[CH];
    __shared__ float rq[CH];
    __shared__ float rs[CH];
    w[t] = (t < 88) ? W1[t * OC + c] : 0.f;
    __syncthreads();
    float q = 0.f;
    if (t < 88) {
        const float* Mr = g_M + t * CH;
        for (int k = 0; k < 88; k++) q += Mr[k] * w[k];
        q *= w[t];
    }
    rq[t] = q;
    rs[t] = (t < 88) ? g_sv[t] * w[t] : 0.f;
    __syncthreads();
    if (t == 0) {
        float Q = 0.f, SW = 0.f;
        for (int i = 0; i < 88; i++) { Q += rq[i]; SW += rs[i]; }
        float b = b1[c];
        float mean = SW / fE + b;
        float ex2 = (Q + 2.f * b * SW) / fE + b * b;
        float var = ex2 - mean * mean;
        g_mean[c] = mean;
        g_scale[c] = gamma[c] * rsqrtf(var + EPSV);
    }
}

// ---------------- node output, 4 nodes per warp iteration -------------------
__global__ void k_out(const float* __restrict__ x, const float* __restrict__ W1,
                      const float* __restrict__ b1, const float* __restrict__ beta,
                      const float* __restrict__ W2, const float* __restrict__ b2,
                      float* __restrict__ out, int N) {
    extern __shared__ float sm[];
    float* W1s = sm;             // 88*128
    float* W2s = sm + 88 * OC;   // 132*64
    int tid = threadIdx.x;
    for (int i = tid; i < 88 * OC; i += blockDim.x) W1s[i] = W1[i];
    for (int i = tid; i < 132 * OUTC; i += blockDim.x) W2s[i] = W2[i];
    __syncthreads();
    int lane = tid & 31;
    int warp = (blockIdx.x * blockDim.x + tid) >> 5;
    int nw = (gridDim.x * blockDim.x) >> 5;
    float mn0 = g_mean[lane], mn1 = g_mean[32 + lane], mn2 = g_mean[64 + lane], mn3 = g_mean[96 + lane];
    float sc0 = g_scale[lane], sc1 = g_scale[32 + lane], sc2 = g_scale[64 + lane], sc3 = g_scale[96 + lane];
    float bt0 = beta[lane], bt1 = beta[32 + lane], bt2 = beta[64 + lane], bt3 = beta[96 + lane];
    float bo0 = b1[lane], bo1 = b1[32 + lane], bo2 = b1[64 + lane], bo3 = b1[96 + lane];
    float bb0 = b2[lane], bb1 = b2[32 + lane];

    for (int n0 = warp * 4; n0 < N; n0 += nw * 4) {
        float sr0[4], sr1[4], sr2[4], rcp[4], tv[4];
#pragma unroll
        for (int m = 0; m < 4; m++) {
            int n = n0 + m;
            if (n < N) {
                const float* so = g_S + (size_t)n * CH;
                sr0[m] = so[lane]; sr1[m] = so[32 + lane]; sr2[m] = so[64 + lane];
                int cnt = g_off[n + 1] - g_off[n];
                tv[m] = (cnt > 0) ? 1.f : 0.f;
                rcp[m] = (cnt > 0) ? 1.f / (float)cnt : 0.f;
            } else { sr0[m] = sr1[m] = sr2[m] = 0.f; tv[m] = 0.f; rcp[m] = 0.f; }
        }
        float a0[4] = {0,0,0,0}, a1[4] = {0,0,0,0}, a2[4] = {0,0,0,0}, a3[4] = {0,0,0,0};
#pragma unroll
        for (int cc = 0; cc < 32; cc++) {
            const float* wr = W1s + cc * OC + lane;
            float w0 = wr[0], w1 = wr[32], w2 = wr[64], w3 = wr[96];
#pragma unroll
            for (int m = 0; m < 4; m++) {
                float v = __shfl_sync(0xffffffffu, sr0[m], cc);
                a0[m] += v * w0; a1[m] += v * w1; a2[m] += v * w2; a3[m] += v * w3;
            }
        }
#pragma unroll
        for (int cc = 0; cc < 32; cc++) {
            const float* wr = W1s + (32 + cc) * OC + lane;
            float w0 = wr[0], w1 = wr[32], w2 = wr[64], w3 = wr[96];
#pragma unroll
            for (int m = 0; m < 4; m++) {
                float v = __shfl_sync(0xffffffffu, sr1[m], cc);
                a0[m] += v * w0; a1[m] += v * w1; a2[m] += v * w2; a3[m] += v * w3;
            }
        }
#pragma unroll
        for (int cc = 0; cc < 24; cc++) {
            const float* wr = W1s + (64 + cc) * OC + lane;
            float w0 = wr[0], w1 = wr[32], w2 = wr[64], w3 = wr[96];
#pragma unroll
            for (int m = 0; m < 4; m++) {
                float v = __shfl_sync(0xffffffffu, sr2[m], cc);
                a0[m] += v * w0; a1[m] += v * w1; a2[m] += v * w2; a3[m] += v * w3;
            }
        }
        float ag0[4], ag1[4], ag2[4], ag3[4];
#pragma unroll
        for (int m = 0; m < 4; m++) {
            ag0[m] = ((a0[m] * rcp[m] + bo0 - mn0) * sc0 + bt0) * tv[m];
            ag1[m] = ((a1[m] * rcp[m] + bo1 - mn1) * sc1 + bt1) * tv[m];
            ag2[m] = ((a2[m] * rcp[m] + bo2 - mn2) * sc2 + bt2) * tv[m];
            ag3[m] = ((a3[m] * rcp[m] + bo3 - mn3) * sc3 + bt3) * tv[m];
        }
        float o0[4], o1[4];
#pragma unroll
        for (int m = 0; m < 4; m++) { o0[m] = bb0; o1[m] = bb1; }
#pragma unroll
        for (int k = 0; k < 4; k++) {
            float wa = W2s[k * OUTC + lane], wb = W2s[k * OUTC + 32 + lane];
#pragma unroll
            for (int m = 0; m < 4; m++) {
                int n = n0 + m;
                float xv = (n < N) ? x[(size_t)n * 4 + k] : 0.f;
                o0[m] += xv * wa; o1[m] += xv * wb;
            }
        }
#pragma unroll
        for (int cc = 0; cc < 32; cc++) {
            const float* wr = W2s + (4 + cc) * OUTC + lane;
            float w0 = wr[0], w1 = wr[32];
#pragma unroll
            for (int m = 0; m < 4; m++) {
                float av = __shfl_sync(0xffffffffu, ag0[m], cc);
                o0[m] += av * w0; o1[m] += av * w1;
            }
        }
#pragma unroll
        for (int cc = 0; cc < 32; cc++) {
            const float* wr = W2s + (36 + cc) * OUTC + lane;
            float w0 = wr[0], w1 = wr[32];
#pragma unroll
            for (int m = 0; m < 4; m++) {
                float av = __shfl_sync(0xffffffffu, ag1[m], cc);
                o0[m] += av * w0; o1[m] += av * w1;
            }
        }
#pragma unroll
        for (int cc = 0; cc < 32; cc++) {
            const float* wr = W2s + (68 + cc) * OUTC + lane;
            float w0 = wr[0], w1 = wr[32];
#pragma unroll
            for (int m = 0; m < 4; m++) {
                float av = __shfl_sync(0xffffffffu, ag2[m], cc);
                o0[m] += av * w0; o1[m] += av * w1;
            }
        }
#pragma unroll
        for (int cc = 0; cc < 32; cc++) {
            const float* wr = W2s + (100 + cc) * OUTC + lane;
            float w0 = wr[0], w1 = wr[32];
#pragma unroll
            for (int m = 0; m < 4; m++) {
                float av = __shfl_sync(0xffffffffu, ag3[m], cc);
                o0[m] += av * w0; o1[m] += av * w1;
            }
        }
#pragma unroll
        for (int m = 0; m < 4; m++) {
            int n = n0 + m;
            if (n < N) {
                out[(size_t)n * 64 + lane] = fmaxf(o0[m], 0.f);
                out[(size_t)n * 64 + 32 + lane] = fmaxf(o1[m], 0.f);
            }
        }
    }
}

// ---------------- launcher --------------------------------------------------
extern "C" void kernel_launch(void* const* d_in, const int* in_sizes, int n_in,
                              void* d_out, int out_size) {
    const float* x     = (const float*)d_in[0];
    const void*  ei    = d_in[1];
    const float* ea    = (const float*)d_in[2];
    const float* W1    = (const float*)d_in[3];
    const float* b1    = (const float*)d_in[4];
    const float* gamma = (const float*)d_in[5];
    const float* beta  = (const float*)d_in[6];
    const float* W2    = (const float*)d_in[7];
    const float* b2    = (const float*)d_in[8];
    float* out = (float*)d_out;
    int N = in_sizes[0] / 4;
    int E = in_sizes[2] / 84;

    k_detect<<<1, 32>>>(ei);
    k_convert<<<512, 256>>>(ei, E);
    k_zero<<<128, 256>>>(N);
    k_hist<<<512, 256>>>(E);
    k_scan<<<1, 1024>>>(N, E);
    k_perm<<<512, 256>>>(E);
    k_agg<<<592, 256>>>(x, ea, N);
    k_Mmma<<<148, 256>>>(x, ea, E);
    k_bn<<<128, 96>>>(W1, b1, gamma, (float)E);
    const int smem = (88 * OC + 132 * OUTC) * 4;  // 78848 B
    cudaFuncSetAttribute(k_out, cudaFuncAttributeMaxDynamicSharedMemorySize, smem);
    k_out<<<296, 256, smem>>>(x, W1, b1, beta, W2, b2, out, N);
}

// round 5
// speedup vs baseline: 1.7573x; 1.6899x over previous
#include <cuda_runtime.h>
#include <cuda_bf16.h>
#include <cstdint>

#define MAXN 50000
#define MAXE 800000
#define CH 96          // padded feature channels (88 real: 4 x + 84 edge_attr)
#define OC 128
#define OUTC 64
#define EPSV 1e-5f

// ---------------- device scratch (static globals: no allocs allowed) -------
__device__ int   g_is64;
__device__ int   g_row[MAXE];
__device__ int   g_col[MAXE];
__device__ int   g_cnt[MAXN];
__device__ int   g_off[MAXN + 1];
__device__ int   g_cur[MAXN];
__device__ int   g_perm[MAXE];
__device__ float g_S[(size_t)MAXN * CH];   // per-node summed features
__device__ float g_M[CH * CH];             // second-moment matrix sum f f^T
__device__ float g_sv[CH];                 // global feature sum s
__device__ float g_mean[OC];
__device__ float g_scale[OC];              // gamma * rsqrt(var+eps)

__device__ __forceinline__ uint32_t smem_u32(const void* p) {
    uint32_t a;
    asm("{ .reg .u64 t; cvta.to.shared.u64 t, %1; cvt.u32.u64 %0, t; }" : "=r"(a) : "l"(p));
    return a;
}

// ---------------- dtype detection: int64 vs int32 edge_index ----------------
__global__ void k_detect(const void* ei) {
    const long long* p = (const long long*)ei;
    int bad = 0;
    for (int i = threadIdx.x; i < 64; i += 32) {
        long long v = p[i];
        if (v < 0 || v >= MAXN) bad = 1;
    }
    unsigned m = __ballot_sync(0xffffffffu, bad);
    if (threadIdx.x == 0) g_is64 = (m == 0) ? 1 : 0;
}

__global__ void k_convert(const void* ei, int E) {
    int is64 = g_is64;
    int i = blockIdx.x * blockDim.x + threadIdx.x;
    int T = gridDim.x * blockDim.x;
    if (is64) {
        const long long* p = (const long long*)ei;
        for (int e = i; e < E; e += T) { g_row[e] = (int)p[e]; g_col[e] = (int)p[E + e]; }
    } else {
        const int* p = (const int*)ei;
        for (int e = i; e < E; e += T) { g_row[e] = p[e]; g_col[e] = p[E + e]; }
    }
}

// ---------------- zero scratch ---------------------------------------------
__global__ void k_zero(int N) {
    int i = blockIdx.x * blockDim.x + threadIdx.x;
    int T = gridDim.x * blockDim.x;
    for (int j = i; j < N; j += T) g_cnt[j] = 0;
    for (int j = i; j < CH * CH; j += T) g_M[j] = 0.f;
    if (i < CH) g_sv[i] = 0.f;
}

__global__ void k_hist(int E) {
    int i = blockIdx.x * blockDim.x + threadIdx.x;
    int T = gridDim.x * blockDim.x;
    for (int e = i; e < E; e += T) atomicAdd(&g_cnt[g_row[e]], 1);
}

// ---------------- exclusive scan (single CTA) ------------------------------
__global__ void k_scan(int N, int E) {
    __shared__ int part[1024];
    int tid = threadIdx.x;
    int chunk = (N + 1023) >> 10;
    int beg = tid * chunk;
    int end = min(beg + chunk, N);
    int s = 0;
    for (int i = beg; i < end; i++) s += g_cnt[i];
    part[tid] = s;
    __syncthreads();
    if (tid == 0) {
        int r = 0;
        for (int i = 0; i < 1024; i++) { int t = part[i]; part[i] = r; r += t; }
        g_off[N] = E;
    }
    __syncthreads();
    int r = part[tid];
    for (int i = beg; i < end; i++) { g_off[i] = r; g_cur[i] = r; r += g_cnt[i]; }
}

__global__ void k_perm(int E) {
    int i = blockIdx.x * blockDim.x + threadIdx.x;
    int T = gridDim.x * blockDim.x;
    for (int e = i; e < E; e += T) {
        int r = g_row[e];
        int p = atomicAdd(&g_cur[r], 1);
        g_perm[p] = e;
    }
}

// ---------------- per-node feature sum (gather, no atomics, 4x MLP) --------
__global__ void k_agg(const float* __restrict__ x, const float* __restrict__ ea,
                      int N) {
    int lane = threadIdx.x & 31;
    int warp = (blockIdx.x * blockDim.x + threadIdx.x) >> 5;
    int nw = (gridDim.x * blockDim.x) >> 5;
    for (int n = warp; n < N; n += nw) {
        int beg = g_off[n], end = g_off[n + 1];
        float a0 = 0.f, a1 = 0.f, a2 = 0.f;
        int j = beg;
        for (; j + 4 <= end; j += 4) {
            int e0 = g_perm[j], e1 = g_perm[j + 1], e2 = g_perm[j + 2], e3 = g_perm[j + 3];
            const float* f0 = ea + (size_t)e0 * 84;
            const float* f1 = ea + (size_t)e1 * 84;
            const float* f2 = ea + (size_t)e2 * 84;
            const float* f3 = ea + (size_t)e3 * 84;
            float p0, p1, p2, p3;
            if (lane < 4) {
                p0 = x[g_col[e0] * 4 + lane]; p1 = x[g_col[e1] * 4 + lane];
                p2 = x[g_col[e2] * 4 + lane]; p3 = x[g_col[e3] * 4 + lane];
            } else {
                p0 = f0[lane - 4]; p1 = f1[lane - 4]; p2 = f2[lane - 4]; p3 = f3[lane - 4];
            }
            float q0 = f0[28 + lane], q1 = f1[28 + lane], q2 = f2[28 + lane], q3 = f3[28 + lane];
            a0 += (p0 + p1) + (p2 + p3);
            a1 += (q0 + q1) + (q2 + q3);
            if (lane < 24) {
                float r0 = f0[60 + lane], r1 = f1[60 + lane], r2 = f2[60 + lane], r3 = f3[60 + lane];
                a2 += (r0 + r1) + (r2 + r3);
            }
        }
        for (; j < end; j++) {
            int e = g_perm[j];
            const float* fe = ea + (size_t)e * 84;
            float v0;
            if (lane < 4) { int col = g_col[e]; v0 = x[col * 4 + lane]; }
            else          { v0 = fe[lane - 4]; }
            a0 += v0;
            a1 += fe[28 + lane];
            if (lane < 24) a2 += fe[60 + lane];
        }
        float* so = g_S + (size_t)n * CH;
        so[lane] = a0;
        so[32 + lane] = a1;
        so[64 + lane] = (lane < 24) ? a2 : 0.f;
    }
}

// ---------------- M = sum_e f f^T via bf16 mma.sync (HMMA) -----------------
// Double-buffered 96x64 bf16 tiles (row stride 144B, conflict-free ldmatrix).
// Warps 2x4: warp covers 48 rows x 24 cols as 3x3 m16n8k16 tiles.
// fp32 accumulators live in registers across all K-chunks; atomicAdd at end.
#define KB 64
#define ROWB 144

__device__ __forceinline__ void ldm_x4(uint32_t* r, uint32_t a) {
    asm volatile("ldmatrix.sync.aligned.m8n8.x4.shared.b16 {%0,%1,%2,%3}, [%4];"
                 : "=r"(r[0]), "=r"(r[1]), "=r"(r[2]), "=r"(r[3]) : "r"(a));
}
__device__ __forceinline__ void ldm_x2(uint32_t* r, uint32_t a) {
    asm volatile("ldmatrix.sync.aligned.m8n8.x2.shared.b16 {%0,%1}, [%2];"
                 : "=r"(r[0]), "=r"(r[1]) : "r"(a));
}
__device__ __forceinline__ void mma_bf16(float* c, const uint32_t* a, const uint32_t* b) {
    asm volatile("mma.sync.aligned.m16n8k16.row.col.f32.bf16.bf16.f32 "
                 "{%0,%1,%2,%3}, {%4,%5,%6,%7}, {%8,%9}, {%0,%1,%2,%3};"
                 : "+f"(c[0]), "+f"(c[1]), "+f"(c[2]), "+f"(c[3])
                 : "r"(a[0]), "r"(a[1]), "r"(a[2]), "r"(a[3]), "r"(b[0]), "r"(b[1]));
}

__global__ void __launch_bounds__(256, 2)
k_Mmma(const float* __restrict__ x, const float* __restrict__ ea, int E) {
    __shared__ __align__(16) char tile[2][CH * ROWB];   // 2 x 13824 B
    int tid = threadIdx.x;
    int lane = tid & 31, w = tid >> 5;
    int warp_m = w >> 2, warp_n = w & 3;   // 2 x 4
    int Rm = warp_m * 48;                  // 3 x 16 rows
    int Rn = warp_n * 24;                  // 3 x 8 cols

    float acc[3][3][4];
#pragma unroll
    for (int i = 0; i < 3; i++)
#pragma unroll
        for (int j = 0; j < 3; j++)
#pragma unroll
            for (int q = 0; q < 4; q++) acc[i][j][q] = 0.f;

    float s0 = 0.f, s1 = 0.f, s2 = 0.f;
    int nchunk = (E + KB - 1) / KB;
    int buf = 0;
    for (int c = blockIdx.x; c < nchunk; c += gridDim.x, buf ^= 1) {
        long long base = (long long)c * KB;
        char* tp = tile[buf];
        // prefetch all 8 row-groups for this warp (24 outstanding LDGs)
        float v0[8], v1[8], v2[8];
#pragma unroll
        for (int u = 0; u < 8; u++) {
            long long e = base + w + u * 8;
            v0[u] = 0.f; v1[u] = 0.f; v2[u] = 0.f;
            if (e < E) {
                const float* fe = ea + e * 84;
                if (lane < 4) v0[u] = x[g_col[e] * 4 + lane];
                else          v0[u] = fe[lane - 4];
                v1[u] = fe[28 + lane];
                if (lane < 24) v2[u] = fe[60 + lane];
            }
        }
#pragma unroll
        for (int u = 0; u < 8; u++) {
            int ee = w + u * 8;
            s0 += v0[u]; s1 += v1[u]; s2 += v2[u];
            *(__nv_bfloat16*)(tp + lane * ROWB + ee * 2) = __float2bfloat16(v0[u]);
            *(__nv_bfloat16*)(tp + (32 + lane) * ROWB + ee * 2) = __float2bfloat16(v1[u]);
            *(__nv_bfloat16*)(tp + (64 + lane) * ROWB + ee * 2) =
                (lane < 24) ? __float2bfloat16(v2[u]) : __nv_bfloat16(0.f);
        }
        __syncthreads();   // stores of buf visible; prior-iteration mma on buf done
        uint32_t tb = smem_u32(tp);
#pragma unroll
        for (int ks = 0; ks < KB / 16; ks++) {
            uint32_t af[3][4], bf[3][2];
#pragma unroll
            for (int i = 0; i < 3; i++) {
                uint32_t addr = tb + (uint32_t)((Rm + i * 16 + (lane & 15)) * ROWB
                                                + ks * 32 + (lane >> 4) * 16);
                ldm_x4(af[i], addr);
            }
#pragma unroll
            for (int j = 0; j < 3; j++) {
                uint32_t addr = tb + (uint32_t)((Rn + j * 8 + (lane & 7)) * ROWB
                                                + ks * 32 + ((lane >> 3) & 1) * 16);
                ldm_x2(bf[j], addr);
            }
#pragma unroll
            for (int i = 0; i < 3; i++)
#pragma unroll
                for (int j = 0; j < 3; j++) mma_bf16(acc[i][j], af[i], bf[j]);
        }
    }
    // writeback
#pragma unroll
    for (int i = 0; i < 3; i++)
#pragma unroll
        for (int j = 0; j < 3; j++) {
            int row = Rm + i * 16 + (lane >> 2);
            int col = Rn + j * 8 + (lane & 3) * 2;
            atomicAdd(&g_M[row * CH + col], acc[i][j][0]);
            atomicAdd(&g_M[row * CH + col + 1], acc[i][j][1]);
            atomicAdd(&g_M[(row + 8) * CH + col], acc[i][j][2]);
            atomicAdd(&g_M[(row + 8) * CH + col + 1], acc[i][j][3]);
        }
    atomicAdd(&g_sv[lane], s0);
    atomicAdd(&g_sv[32 + lane], s1);
    if (lane < 24) atomicAdd(&g_sv[64 + lane], s2);
}

// ---------------- BN stats --------------------------------------------------
__global__ void k_bn(const float* __restrict__ W1, const float* __restrict__ b1,
                     const float* __restrict__ gamma, float fE) {
    int c = blockIdx.x;
    int t = threadIdx.x;  // 96 threads
    __shared__ float w[CH];
    __shared__ float rq[CH];
    __shared__ float rs[CH];
    w[t] = (t < 88) ? W1[t * OC + c] : 0.f;
    __syncthreads();
    float q = 0.f;
    if (t < 88) {
        const float* Mr = g_M + t * CH;
        for (int k = 0; k < 88; k++) q += Mr[k] * w[k];
        q *= w[t];
    }
    rq[t] = q;
    rs[t] = (t < 88) ? g_sv[t] * w[t] : 0.f;
    __syncthreads();
    if (t == 0) {
        float Q = 0.f, SW = 0.f;
        for (int i = 0; i < 88; i++) { Q += rq[i]; SW += rs[i]; }
        float b = b1[c];
        float mean = SW / fE + b;
        float ex2 = (Q + 2.f * b * SW) / fE + b * b;
        float var = ex2 - mean * mean;
        g_mean[c] = mean;
        g_scale[c] = gamma[c] * rsqrtf(var + EPSV);
    }
}

// ---------------- node output, 4 nodes per warp iteration -------------------
__global__ void k_out(const float* __restrict__ x, const float* __restrict__ W1,
                      const float* __restrict__ b1, const float* __restrict__ beta,
                      const float* __restrict__ W2, const float* __restrict__ b2,
                      float* __restrict__ out, int N) {
    extern __shared__ float sm[];
    float* W1s = sm;             // 88*128
    float* W2s = sm + 88 * OC;   // 132*64
    int tid = threadIdx.x;
    for (int i = tid; i < 88 * OC; i += blockDim.x) W1s[i] = W1[i];
    for (int i = tid; i < 132 * OUTC; i += blockDim.x) W2s[i] = W2[i];
    __syncthreads();
    int lane = tid & 31;
    int warp = (blockIdx.x * blockDim.x + tid) >> 5;
    int nw = (gridDim.x * blockDim.x) >> 5;
    float mn0 = g_mean[lane], mn1 = g_mean[32 + lane], mn2 = g_mean[64 + lane], mn3 = g_mean[96 + lane];
    float sc0 = g_scale[lane], sc1 = g_scale[32 + lane], sc2 = g_scale[64 + lane], sc3 = g_scale[96 + lane];
    float bt0 = beta[lane], bt1 = beta[32 + lane], bt2 = beta[64 + lane], bt3 = beta[96 + lane];
    float bo0 = b1[lane], bo1 = b1[32 + lane], bo2 = b1[64 + lane], bo3 = b1[96 + lane];
    float bb0 = b2[lane], bb1 = b2[32 + lane];

    for (int n0 = warp * 4; n0 < N; n0 += nw * 4) {
        float sr0[4], sr1[4], sr2[4], rcp[4], tv[4];
#pragma unroll
        for (int m = 0; m < 4; m++) {
            int n = n0 + m;
            if (n < N) {
                const float* so = g_S + (size_t)n * CH;
                sr0[m] = so[lane]; sr1[m] = so[32 + lane]; sr2[m] = so[64 + lane];
                int cnt = g_off[n + 1] - g_off[n];
                tv[m] = (cnt > 0) ? 1.f : 0.f;
                rcp[m] = (cnt > 0) ? 1.f / (float)cnt : 0.f;
            } else { sr0[m] = sr1[m] = sr2[m] = 0.f; tv[m] = 0.f; rcp[m] = 0.f; }
        }
        float a0[4] = {0,0,0,0}, a1[4] = {0,0,0,0}, a2[4] = {0,0,0,0}, a3[4] = {0,0,0,0};
#pragma unroll
        for (int cc = 0; cc < 32; cc++) {
            const float* wr = W1s + cc * OC + lane;
            float w0 = wr[0], w1 = wr[32], w2 = wr[64], w3 = wr[96];
#pragma unroll
            for (int m = 0; m < 4; m++) {
                float v = __shfl_sync(0xffffffffu, sr0[m], cc);
                a0[m] += v * w0; a1[m] += v * w1; a2[m] += v * w2; a3[m] += v * w3;
            }
        }
#pragma unroll
        for (int cc = 0; cc < 32; cc++) {
            const float* wr = W1s + (32 + cc) * OC + lane;
            float w0 = wr[0], w1 = wr[32], w2 = wr[64], w3 = wr[96];
#pragma unroll
            for (int m = 0; m < 4; m++) {
                float v = __shfl_sync(0xffffffffu, sr1[m], cc);
                a0[m] += v * w0; a1[m] += v * w1; a2[m] += v * w2; a3[m] += v * w3;
            }
        }
#pragma unroll
        for (int cc = 0; cc < 24; cc++) {
            const float* wr = W1s + (64 + cc) * OC + lane;
            float w0 = wr[0], w1 = wr[32], w2 = wr[64], w3 = wr[96];
#pragma unroll
            for (int m = 0; m < 4; m++) {
                float v = __shfl_sync(0xffffffffu, sr2[m], cc);
                a0[m] += v * w0; a1[m] += v * w1; a2[m] += v * w2; a3[m] += v * w3;
            }
        }
        float ag0[4], ag1[4], ag2[4], ag3[4];
#pragma unroll
        for (int m = 0; m < 4; m++) {
            ag0[m] = ((a0[m] * rcp[m] + bo0 - mn0) * sc0 + bt0) * tv[m];
            ag1[m] = ((a1[m] * rcp[m] + bo1 - mn1) * sc1 + bt1) * tv[m];
            ag2[m] = ((a2[m] * rcp[m] + bo2 - mn2) * sc2 + bt2) * tv[m];
            ag3[m] = ((a3[m] * rcp[m] + bo3 - mn3) * sc3 + bt3) * tv[m];
        }
        float o0[4], o1[4];
#pragma unroll
        for (int m = 0; m < 4; m++) { o0[m] = bb0; o1[m] = bb1; }
#pragma unroll
        for (int k = 0; k < 4; k++) {
            float wa = W2s[k * OUTC + lane], wb = W2s[k * OUTC + 32 + lane];
#pragma unroll
            for (int m = 0; m < 4; m++) {
                int n = n0 + m;
                float xv = (n < N) ? x[(size_t)n * 4 + k] : 0.f;
                o0[m] += xv * wa; o1[m] += xv * wb;
            }
        }
#pragma unroll
        for (int cc = 0; cc < 32; cc++) {
            const float* wr = W2s + (4 + cc) * OUTC + lane;
            float w0 = wr[0], w1 = wr[32];
#pragma unroll
            for (int m = 0; m < 4; m++) {
                float av = __shfl_sync(0xffffffffu, ag0[m], cc);
                o0[m] += av * w0; o1[m] += av * w1;
            }
        }
#pragma unroll
        for (int cc = 0; cc < 32; cc++) {
            const float* wr = W2s + (36 + cc) * OUTC + lane;
            float w0 = wr[0], w1 = wr[32];
#pragma unroll
            for (int m = 0; m < 4; m++) {
                float av = __shfl_sync(0xffffffffu, ag1[m], cc);
                o0[m] += av * w0; o1[m] += av * w1;
            }
        }
#pragma unroll
        for (int cc = 0; cc < 32; cc++) {
            const float* wr = W2s + (68 + cc) * OUTC + lane;
            float w0 = wr[0], w1 = wr[32];
#pragma unroll
            for (int m = 0; m < 4; m++) {
                float av = __shfl_sync(0xffffffffu, ag2[m], cc);
                o0[m] += av * w0; o1[m] += av * w1;
            }
        }
#pragma unroll
        for (int cc = 0; cc < 32; cc++) {
            const float* wr = W2s + (100 + cc) * OUTC + lane;
            float w0 = wr[0], w1 = wr[32];
#pragma unroll
            for (int m = 0; m < 4; m++) {
                float av = __shfl_sync(0xffffffffu, ag3[m], cc);
                o0[m] += av * w0; o1[m] += av * w1;
            }
        }
#pragma unroll
        for (int m = 0; m < 4; m++) {
            int n = n0 + m;
            if (n < N) {
                out[(size_t)n * 64 + lane] = fmaxf(o0[m], 0.f);
                out[(size_t)n * 64 + 32 + lane] = fmaxf(o1[m], 0.f);
            }
        }
    }
}

// ---------------- launcher --------------------------------------------------
extern "C" void kernel_launch(void* const* d_in, const int* in_sizes, int n_in,
                              void* d_out, int out_size) {
    const float* x     = (const float*)d_in[0];
    const void*  ei    = d_in[1];
    const float* ea    = (const float*)d_in[2];
    const float* W1    = (const float*)d_in[3];
    const float* b1    = (const float*)d_in[4];
    const float* gamma = (const float*)d_in[5];
    const float* beta  = (const float*)d_in[6];
    const float* W2    = (const float*)d_in[7];
    const float* b2    = (const float*)d_in[8];
    float* out = (float*)d_out;
    int N = in_sizes[0] / 4;
    int E = in_sizes[2] / 84;

    k_detect<<<1, 32>>>(ei);
    k_convert<<<512, 256>>>(ei, E);
    k_zero<<<128, 256>>>(N);
    k_hist<<<512, 256>>>(E);
    k_scan<<<1, 1024>>>(N, E);
    k_perm<<<512, 256>>>(E);
    k_agg<<<592, 256>>>(x, ea, N);
    k_Mmma<<<296, 256>>>(x, ea, E);
    k_bn<<<128, 96>>>(W1, b1, gamma, (float)E);
    const int smem = (88 * OC + 132 * OUTC) * 4;  // 78848 B
    cudaFuncSetAttribute(k_out, cudaFuncAttributeMaxDynamicSharedMemorySize, smem);
    k_out<<<296, 256, smem>>>(x, W1, b1, beta, W2, b2, out, N);
}

// round 6
// speedup vs baseline: 2.2352x; 1.2719x over previous
#include <cuda_runtime.h>
#include <cuda_bf16.h>
#include <cstdint>

#define MAXN 50000
#define MAXE 800000
#define CH 96          // padded feature channels (88 real: 4 x + 84 edge_attr)
#define OC 128
#define OUTC 64
#define EPSV 1e-5f

// ---------------- device scratch (static globals: no allocs allowed) -------
__device__ int   g_is64;
__device__ int   g_row[MAXE];
__device__ int   g_col[MAXE];
__device__ int   g_cnt[MAXN];
__device__ int   g_off[MAXN + 1];
__device__ int   g_cur[MAXN];
__device__ int   g_perm[MAXE];
__device__ float g_S[(size_t)MAXN * CH];   // per-node summed features
__device__ float g_M[CH * CH];             // second-moment matrix sum f f^T
__device__ float g_sv[CH];                 // global feature sum s
__device__ float g_mean[OC];
__device__ float g_scale[OC];              // gamma * rsqrt(var+eps)

__device__ __forceinline__ uint32_t smem_u32(const void* p) {
    uint32_t a;
    asm("{ .reg .u64 t; cvta.to.shared.u64 t, %1; cvt.u32.u64 %0, t; }" : "=r"(a) : "l"(p));
    return a;
}

// ---------------- dtype detection: int64 vs int32 edge_index ----------------
__global__ void k_detect(const void* ei) {
    const long long* p = (const long long*)ei;
    int bad = 0;
    for (int i = threadIdx.x; i < 64; i += 32) {
        long long v = p[i];
        if (v < 0 || v >= MAXN) bad = 1;
    }
    unsigned m = __ballot_sync(0xffffffffu, bad);
    if (threadIdx.x == 0) g_is64 = (m == 0) ? 1 : 0;
}

// ---------------- zero scratch ---------------------------------------------
__global__ void k_zero(int N) {
    int i = blockIdx.x * blockDim.x + threadIdx.x;
    int T = gridDim.x * blockDim.x;
    for (int j = i; j < N; j += T) g_cnt[j] = 0;
    for (int j = i; j < CH * CH; j += T) g_M[j] = 0.f;
    if (i < CH) g_sv[i] = 0.f;
}

// ---------------- convert + histogram fused ---------------------------------
__global__ void k_convhist(const void* ei, int E) {
    int is64 = g_is64;
    int i = blockIdx.x * blockDim.x + threadIdx.x;
    int T = gridDim.x * blockDim.x;
    if (is64) {
        const long long* p = (const long long*)ei;
        for (int e = i; e < E; e += T) {
            int r = (int)p[e];
            g_row[e] = r; g_col[e] = (int)p[E + e];
            atomicAdd(&g_cnt[r], 1);
        }
    } else {
        const int* p = (const int*)ei;
        for (int e = i; e < E; e += T) {
            int r = p[e];
            g_row[e] = r; g_col[e] = p[E + e];
            atomicAdd(&g_cnt[r], 1);
        }
    }
}

// ---------------- exclusive scan (single CTA, parallel) --------------------
__global__ void k_scan(int N, int E) {
    __shared__ int part[1024];
    int tid = threadIdx.x;
    int chunk = (N + 1023) >> 10;
    int beg = tid * chunk;
    int end = min(beg + chunk, N);
    int s = 0;
    for (int i = beg; i < end; i++) s += g_cnt[i];
    part[tid] = s;
    __syncthreads();
    for (int d = 1; d < 1024; d <<= 1) {           // Hillis-Steele inclusive
        int v = (tid >= d) ? part[tid - d] : 0;
        __syncthreads();
        part[tid] += v;
        __syncthreads();
    }
    int r = (tid > 0) ? part[tid - 1] : 0;          // exclusive
    for (int i = beg; i < end; i++) { g_off[i] = r; g_cur[i] = r; r += g_cnt[i]; }
    if (tid == 0) g_off[N] = E;
}

__global__ void k_perm(int E) {
    int i = blockIdx.x * blockDim.x + threadIdx.x;
    int T = gridDim.x * blockDim.x;
    for (int e = i; e < E; e += T) {
        int r = g_row[e];
        int p = atomicAdd(&g_cur[r], 1);
        g_perm[p] = e;
    }
}

// ---------------- per-node feature sum (gather, predicated unroll-8) -------
__global__ void k_agg(const float* __restrict__ x, const float* __restrict__ ea,
                      int N) {
    int lane = threadIdx.x & 31;
    int warp = (blockIdx.x * blockDim.x + threadIdx.x) >> 5;
    int nw = (gridDim.x * blockDim.x) >> 5;
    for (int n = warp; n < N; n += nw) {
        int beg = g_off[n], end = g_off[n + 1];
        float a0 = 0.f, a1 = 0.f, a2 = 0.f;
        if (beg < end) {
            int last = end - 1;
            for (int j = beg; j < end; j += 8) {
                int e[8]; float msk[8];
#pragma unroll
                for (int u = 0; u < 8; u++) {
                    int idx = j + u;
                    msk[u] = (idx < end) ? 1.f : 0.f;
                    e[u] = g_perm[(idx < end) ? idx : last];
                }
                float p[8], q[8], r[8];
#pragma unroll
                for (int u = 0; u < 8; u++) {
                    const float* fe = ea + (size_t)e[u] * 84;
                    if (lane < 4) p[u] = x[g_col[e[u]] * 4 + lane];
                    else          p[u] = __ldcs(fe + lane - 4);
                    q[u] = __ldcs(fe + 28 + lane);
                    r[u] = (lane < 24) ? __ldcs(fe + 60 + lane) : 0.f;
                }
#pragma unroll
                for (int u = 0; u < 8; u++) {
                    a0 += msk[u] * p[u];
                    a1 += msk[u] * q[u];
                    a2 += msk[u] * r[u];
                }
            }
        }
        float* so = g_S + (size_t)n * CH;
        so[lane] = a0;
        so[32 + lane] = a1;
        so[64 + lane] = (lane < 24) ? a2 : 0.f;
    }
}

// ---------------- M = sum_e f f^T via bf16 mma.sync (HMMA) -----------------
// Double-buffered 96x128 bf16 tiles (row stride 272B, conflict-free ldmatrix).
// Warps 2x4: warp covers 48 rows x 24 cols as 3x3 m16n8k16 tiles.
#define KB 128
#define ROWB 272
#define TILE_B (CH * ROWB)   // 26112

__device__ __forceinline__ void ldm_x4(uint32_t* r, uint32_t a) {
    asm volatile("ldmatrix.sync.aligned.m8n8.x4.shared.b16 {%0,%1,%2,%3}, [%4];"
                 : "=r"(r[0]), "=r"(r[1]), "=r"(r[2]), "=r"(r[3]) : "r"(a));
}
__device__ __forceinline__ void ldm_x2(uint32_t* r, uint32_t a) {
    asm volatile("ldmatrix.sync.aligned.m8n8.x2.shared.b16 {%0,%1}, [%2];"
                 : "=r"(r[0]), "=r"(r[1]) : "r"(a));
}
__device__ __forceinline__ void mma_bf16(float* c, const uint32_t* a, const uint32_t* b) {
    asm volatile("mma.sync.aligned.m16n8k16.row.col.f32.bf16.bf16.f32 "
                 "{%0,%1,%2,%3}, {%4,%5,%6,%7}, {%8,%9}, {%0,%1,%2,%3};"
                 : "+f"(c[0]), "+f"(c[1]), "+f"(c[2]), "+f"(c[3])
                 : "r"(a[0]), "r"(a[1]), "r"(a[2]), "r"(a[3]), "r"(b[0]), "r"(b[1]));
}

__global__ void __launch_bounds__(256, 2)
k_Mmma(const float* __restrict__ x, const float* __restrict__ ea, int E) {
    extern __shared__ __align__(16) char dsm[];   // 2 * TILE_B
    int tid = threadIdx.x;
    int lane = tid & 31, w = tid >> 5;
    int warp_m = w >> 2, warp_n = w & 3;   // 2 x 4
    int Rm = warp_m * 48;                  // 3 x 16 rows
    int Rn = warp_n * 24;                  // 3 x 8 cols

    float acc[3][3][4];
#pragma unroll
    for (int i = 0; i < 3; i++)
#pragma unroll
        for (int j = 0; j < 3; j++)
#pragma unroll
            for (int q = 0; q < 4; q++) acc[i][j][q] = 0.f;

    float s0 = 0.f, s1 = 0.f, s2 = 0.f;
    int nchunk = (E + KB - 1) / KB;
    int buf = 0;
    for (int c = blockIdx.x; c < nchunk; c += gridDim.x, buf ^= 1) {
        long long base = (long long)c * KB;
        char* tp = dsm + buf * TILE_B;
        // warp w owns contiguous edges [w*16, w*16+16); two prefetch waves of 8
#pragma unroll
        for (int half = 0; half < 2; half++) {
            float v0[8], v1[8], v2[8];
#pragma unroll
            for (int u = 0; u < 8; u++) {
                long long e = base + w * 16 + half * 8 + u;
                v0[u] = 0.f; v1[u] = 0.f; v2[u] = 0.f;
                if (e < E) {
                    const float* fe = ea + e * 84;
                    if (lane < 4) v0[u] = x[g_col[e] * 4 + lane];
                    else          v0[u] = __ldcs(fe + lane - 4);
                    v1[u] = __ldcs(fe + 28 + lane);
                    if (lane < 24) v2[u] = __ldcs(fe + 60 + lane);
                }
            }
#pragma unroll
            for (int u = 0; u < 8; u++) {
                int ee = w * 16 + half * 8 + u;
                s0 += v0[u]; s1 += v1[u]; s2 += v2[u];
                *(__nv_bfloat16*)(tp + lane * ROWB + ee * 2) = __float2bfloat16(v0[u]);
                *(__nv_bfloat16*)(tp + (32 + lane) * ROWB + ee * 2) = __float2bfloat16(v1[u]);
                *(__nv_bfloat16*)(tp + (64 + lane) * ROWB + ee * 2) =
                    (lane < 24) ? __float2bfloat16(v2[u]) : __nv_bfloat16(0.f);
            }
        }
        __syncthreads();   // stores of buf visible; prior-iteration mma on buf done
        uint32_t tb = smem_u32(tp);
#pragma unroll
        for (int ks = 0; ks < KB / 16; ks++) {
            uint32_t af[3][4], bf[3][2];
#pragma unroll
            for (int i = 0; i < 3; i++) {
                uint32_t addr = tb + (uint32_t)((Rm + i * 16 + (lane & 15)) * ROWB
                                                + ks * 32 + (lane >> 4) * 16);
                ldm_x4(af[i], addr);
            }
#pragma unroll
            for (int j = 0; j < 3; j++) {
                uint32_t addr = tb + (uint32_t)((Rn + j * 8 + (lane & 7)) * ROWB
                                                + ks * 32 + ((lane >> 3) & 1) * 16);
                ldm_x2(bf[j], addr);
            }
#pragma unroll
            for (int i = 0; i < 3; i++)
#pragma unroll
                for (int j = 0; j < 3; j++) mma_bf16(acc[i][j], af[i], bf[j]);
        }
    }
    // writeback
#pragma unroll
    for (int i = 0; i < 3; i++)
#pragma unroll
        for (int j = 0; j < 3; j++) {
            int row = Rm + i * 16 + (lane >> 2);
            int col = Rn + j * 8 + (lane & 3) * 2;
            atomicAdd(&g_M[row * CH + col], acc[i][j][0]);
            atomicAdd(&g_M[row * CH + col + 1], acc[i][j][1]);
            atomicAdd(&g_M[(row + 8) * CH + col], acc[i][j][2]);
            atomicAdd(&g_M[(row + 8) * CH + col + 1], acc[i][j][3]);
        }
    atomicAdd(&g_sv[lane], s0);
    atomicAdd(&g_sv[32 + lane], s1);
    if (lane < 24) atomicAdd(&g_sv[64 + lane], s2);
}

// ---------------- BN stats --------------------------------------------------
__global__ void k_bn(const float* __restrict__ W1, const float* __restrict__ b1,
                     const float* __restrict__ gamma, float fE) {
    int c = blockIdx.x;
    int t = threadIdx.x;  // 96 threads
    __shared__ float w[CH];
    __shared__ float rq[CH];
    __shared__ float rs[CH];
    w[t] = (t < 88) ? W1[t * OC + c] : 0.f;
    __syncthreads();
    float q = 0.f;
    if (t < 88) {
        const float* Mr = g_M + t * CH;
        for (int k = 0; k < 88; k++) q += Mr[k] * w[k];
        q *= w[t];
    }
    rq[t] = q;
    rs[t] = (t < 88) ? g_sv[t] * w[t] : 0.f;
    __syncthreads();
    if (t == 0) {
        float Q = 0.f, SW = 0.f;
        for (int i = 0; i < 88; i++) { Q += rq[i]; SW += rs[i]; }
        float b = b1[c];
        float mean = SW / fE + b;
        float ex2 = (Q + 2.f * b * SW) / fE + b * b;
        float var = ex2 - mean * mean;
        g_mean[c] = mean;
        g_scale[c] = gamma[c] * rsqrtf(var + EPSV);
    }
}

// ---------------- node output, 4 nodes per warp iteration -------------------
__global__ void k_out(const float* __restrict__ x, const float* __restrict__ W1,
                      const float* __restrict__ b1, const float* __restrict__ beta,
                      const float* __restrict__ W2, const float* __restrict__ b2,
                      float* __restrict__ out, int N) {
    extern __shared__ float sm[];
    float* W1s = sm;             // 88*128
    float* W2s = sm + 88 * OC;   // 132*64
    int tid = threadIdx.x;
    for (int i = tid; i < 88 * OC; i += blockDim.x) W1s[i] = W1[i];
    for (int i = tid; i < 132 * OUTC; i += blockDim.x) W2s[i] = W2[i];
    __syncthreads();
    int lane = tid & 31;
    int warp = (blockIdx.x * blockDim.x + tid) >> 5;
    int nw = (gridDim.x * blockDim.x) >> 5;
    float mn0 = g_mean[lane], mn1 = g_mean[32 + lane], mn2 = g_mean[64 + lane], mn3 = g_mean[96 + lane];
    float sc0 = g_scale[lane], sc1 = g_scale[32 + lane], sc2 = g_scale[64 + lane], sc3 = g_scale[96 + lane];
    float bt0 = beta[lane], bt1 = beta[32 + lane], bt2 = beta[64 + lane], bt3 = beta[96 + lane];
    float bo0 = b1[lane], bo1 = b1[32 + lane], bo2 = b1[64 + lane], bo3 = b1[96 + lane];
    float bb0 = b2[lane], bb1 = b2[32 + lane];

    for (int n0 = warp * 4; n0 < N; n0 += nw * 4) {
        float sr0[4], sr1[4], sr2[4], rcp[4], tv[4];
#pragma unroll
        for (int m = 0; m < 4; m++) {
            int n = n0 + m;
            if (n < N) {
                const float* so = g_S + (size_t)n * CH;
                sr0[m] = so[lane]; sr1[m] = so[32 + lane]; sr2[m] = so[64 + lane];
                int cnt = g_off[n + 1] - g_off[n];
                tv[m] = (cnt > 0) ? 1.f : 0.f;
                rcp[m] = (cnt > 0) ? 1.f / (float)cnt : 0.f;
            } else { sr0[m] = sr1[m] = sr2[m] = 0.f; tv[m] = 0.f; rcp[m] = 0.f; }
        }
        float a0[4] = {0,0,0,0}, a1[4] = {0,0,0,0}, a2[4] = {0,0,0,0}, a3[4] = {0,0,0,0};
#pragma unroll
        for (int cc = 0; cc < 32; cc++) {
            const float* wr = W1s + cc * OC + lane;
            float w0 = wr[0], w1 = wr[32], w2 = wr[64], w3 = wr[96];
#pragma unroll
            for (int m = 0; m < 4; m++) {
                float v = __shfl_sync(0xffffffffu, sr0[m], cc);
                a0[m] += v * w0; a1[m] += v * w1; a2[m] += v * w2; a3[m] += v * w3;
            }
        }
#pragma unroll
        for (int cc = 0; cc < 32; cc++) {
            const float* wr = W1s + (32 + cc) * OC + lane;
            float w0 = wr[0], w1 = wr[32], w2 = wr[64], w3 = wr[96];
#pragma unroll
            for (int m = 0; m < 4; m++) {
                float v = __shfl_sync(0xffffffffu, sr1[m], cc);
                a0[m] += v * w0; a1[m] += v * w1; a2[m] += v * w2; a3[m] += v * w3;
            }
        }
#pragma unroll
        for (int cc = 0; cc < 24; cc++) {
            const float* wr = W1s + (64 + cc) * OC + lane;
            float w0 = wr[0], w1 = wr[32], w2 = wr[64], w3 = wr[96];
#pragma unroll
            for (int m = 0; m < 4; m++) {
                float v = __shfl_sync(0xffffffffu, sr2[m], cc);
                a0[m] += v * w0; a1[m] += v * w1; a2[m] += v * w2; a3[m] += v * w3;
            }
        }
        float ag0[4], ag1[4], ag2[4], ag3[4];
#pragma unroll
        for (int m = 0; m < 4; m++) {
            ag0[m] = ((a0[m] * rcp[m] + bo0 - mn0) * sc0 + bt0) * tv[m];
            ag1[m] = ((a1[m] * rcp[m] + bo1 - mn1) * sc1 + bt1) * tv[m];
            ag2[m] = ((a2[m] * rcp[m] + bo2 - mn2) * sc2 + bt2) * tv[m];
            ag3[m] = ((a3[m] * rcp[m] + bo3 - mn3) * sc3 + bt3) * tv[m];
        }
        float o0[4], o1[4];
#pragma unroll
        for (int m = 0; m < 4; m++) { o0[m] = bb0; o1[m] = bb1; }
#pragma unroll
        for (int k = 0; k < 4; k++) {
            float wa = W2s[k * OUTC + lane], wb = W2s[k * OUTC + 32 + lane];
#pragma unroll
            for (int m = 0; m < 4; m++) {
                int n = n0 + m;
                float xv = (n < N) ? x[(size_t)n * 4 + k] : 0.f;
                o0[m] += xv * wa; o1[m] += xv * wb;
            }
        }
#pragma unroll
        for (int cc = 0; cc < 32; cc++) {
            const float* wr = W2s + (4 + cc) * OUTC + lane;
            float w0 = wr[0], w1 = wr[32];
#pragma unroll
            for (int m = 0; m < 4; m++) {
                float av = __shfl_sync(0xffffffffu, ag0[m], cc);
                o0[m] += av * w0; o1[m] += av * w1;
            }
        }
#pragma unroll
        for (int cc = 0; cc < 32; cc++) {
            const float* wr = W2s + (36 + cc) * OUTC + lane;
            float w0 = wr[0], w1 = wr[32];
#pragma unroll
            for (int m = 0; m < 4; m++) {
                float av = __shfl_sync(0xffffffffu, ag1[m], cc);
                o0[m] += av * w0; o1[m] += av * w1;
            }
        }
#pragma unroll
        for (int cc = 0; cc < 32; cc++) {
            const float* wr = W2s + (68 + cc) * OUTC + lane;
            float w0 = wr[0], w1 = wr[32];
#pragma unroll
            for (int m = 0; m < 4; m++) {
                float av = __shfl_sync(0xffffffffu, ag2[m], cc);
                o0[m] += av * w0; o1[m] += av * w1;
            }
        }
#pragma unroll
        for (int cc = 0; cc < 32; cc++) {
            const float* wr = W2s + (100 + cc) * OUTC + lane;
            float w0 = wr[0], w1 = wr[32];
#pragma unroll
            for (int m = 0; m < 4; m++) {
                float av = __shfl_sync(0xffffffffu, ag3[m], cc);
                o0[m] += av * w0; o1[m] += av * w1;
            }
        }
#pragma unroll
        for (int m = 0; m < 4; m++) {
            int n = n0 + m;
            if (n < N) {
                out[(size_t)n * 64 + lane] = fmaxf(o0[m], 0.f);
                out[(size_t)n * 64 + 32 + lane] = fmaxf(o1[m], 0.f);
            }
        }
    }
}

// ---------------- launcher --------------------------------------------------
extern "C" void kernel_launch(void* const* d_in, const int* in_sizes, int n_in,
                              void* d_out, int out_size) {
    const float* x     = (const float*)d_in[0];
    const void*  ei    = d_in[1];
    const float* ea    = (const float*)d_in[2];
    const float* W1    = (const float*)d_in[3];
    const float* b1    = (const float*)d_in[4];
    const float* gamma = (const float*)d_in[5];
    const float* beta  = (const float*)d_in[6];
    const float* W2    = (const float*)d_in[7];
    const float* b2    = (const float*)d_in[8];
    float* out = (float*)d_out;
    int N = in_sizes[0] / 4;
    int E = in_sizes[2] / 84;

    k_detect<<<1, 32>>>(ei);
    k_zero<<<128, 256>>>(N);
    k_convhist<<<512, 256>>>(ei, E);
    k_scan<<<1, 1024>>>(N, E);
    k_perm<<<512, 256>>>(E);
    k_agg<<<1184, 256>>>(x, ea, N);
    const int msmem = 2 * TILE_B;   // 52224 B
    cudaFuncSetAttribute(k_Mmma, cudaFuncAttributeMaxDynamicSharedMemorySize, msmem);
    k_Mmma<<<296, 256, msmem>>>(x, ea, E);
    k_bn<<<128, 96>>>(W1, b1, gamma, (float)E);
    const int smem = (88 * OC + 132 * OUTC) * 4;  // 78848 B
    cudaFuncSetAttribute(k_out, cudaFuncAttributeMaxDynamicSharedMemorySize, smem);
    k_out<<<296, 256, smem>>>(x, W1, b1, beta, W2, b2, out, N);
}

// round 7
// speedup vs baseline: 2.8731x; 1.2854x over previous
#include <cuda_runtime.h>
#include <cuda_bf16.h>
#include <cstdint>

#define MAXN 50000
#define MAXE 800000
#define CH 96          // padded feature channels (88 real: 4 x + 84 edge_attr)
#define OC 128
#define OUTC 64
#define EPSV 1e-5f
#define SCAN_CH 2048   // elements per scan CTA

// ---------------- device scratch (static globals: no allocs allowed) -------
__device__ int   g_is64;
__device__ int   g_row[MAXE];
__device__ int   g_col[MAXE];
__device__ int   g_cnt[MAXN];
__device__ int   g_off[MAXN + 1];
__device__ int   g_cur[MAXN];
__device__ int   g_perm[MAXE];
__device__ int   g_blk[64];
__device__ int   g_blkoff[64];
__device__ float g_S[(size_t)MAXN * CH];   // per-node summed features
__device__ float g_M[CH * CH];             // second-moment matrix sum f f^T
__device__ float g_sv[CH];                 // global feature sum s
__device__ float g_mean[OC];
__device__ float g_scale[OC];              // gamma * rsqrt(var+eps)

__device__ __forceinline__ uint32_t smem_u32(const void* p) {
    uint32_t a;
    asm("{ .reg .u64 t; cvta.to.shared.u64 t, %1; cvt.u32.u64 %0, t; }" : "=r"(a) : "l"(p));
    return a;
}

// ---------------- host-side stream/event set (created once, pre-main) ------
struct HxStreams {
    cudaStream_t s1;
    cudaEvent_t evFork, evJoin;
    HxStreams() {
        cudaStreamCreateWithFlags(&s1, cudaStreamNonBlocking);
        cudaEventCreateWithFlags(&evFork, cudaEventDisableTiming);
        cudaEventCreateWithFlags(&evJoin, cudaEventDisableTiming);
    }
};
static HxStreams g_hx;

// ---------------- dtype detection: int64 vs int32 edge_index ----------------
__global__ void k_detect(const void* ei) {
    const long long* p = (const long long*)ei;
    int bad = 0;
    for (int i = threadIdx.x; i < 64; i += 32) {
        long long v = p[i];
        if (v < 0 || v >= MAXN) bad = 1;
    }
    unsigned m = __ballot_sync(0xffffffffu, bad);
    if (threadIdx.x == 0) g_is64 = (m == 0) ? 1 : 0;
}

// ---------------- zero scratch ---------------------------------------------
__global__ void k_zero(int N) {
    int i = blockIdx.x * blockDim.x + threadIdx.x;
    int T = gridDim.x * blockDim.x;
    for (int j = i; j < N; j += T) g_cnt[j] = 0;
    for (int j = i; j < CH * CH; j += T) g_M[j] = 0.f;
    if (i < CH) g_sv[i] = 0.f;
}

// ---------------- convert + histogram fused ---------------------------------
__global__ void k_convhist(const void* ei, int E) {
    int is64 = g_is64;
    int i = blockIdx.x * blockDim.x + threadIdx.x;
    int T = gridDim.x * blockDim.x;
    if (is64) {
        const long long* p = (const long long*)ei;
        for (int e = i; e < E; e += T) {
            int r = (int)p[e];
            g_row[e] = r; g_col[e] = (int)p[E + e];
            atomicAdd(&g_cnt[r], 1);
        }
    } else {
        const int* p = (const int*)ei;
        for (int e = i; e < E; e += T) {
            int r = p[e];
            g_row[e] = r; g_col[e] = p[E + e];
            atomicAdd(&g_cnt[r], 1);
        }
    }
}

// ---------------- multi-CTA exclusive scan ----------------------------------
// Phase A: each CTA scans 2048 counts, writes local-exclusive g_off + block sum
__global__ void k_scanA(int N) {
    __shared__ int sc[1024];
    int b = blockIdx.x, t = threadIdx.x;
    int i0 = b * SCAN_CH + t * 2;
    int c0 = (i0 < N) ? g_cnt[i0] : 0;
    int c1 = (i0 + 1 < N) ? g_cnt[i0 + 1] : 0;
    int s = c0 + c1;
    sc[t] = s;
    __syncthreads();
#pragma unroll
    for (int d = 1; d < 1024; d <<= 1) {
        int v = (t >= d) ? sc[t - d] : 0;
        __syncthreads();
        sc[t] += v;
        __syncthreads();
    }
    int excl = sc[t] - s;
    if (i0 < N) g_off[i0] = excl;
    if (i0 + 1 < N) g_off[i0 + 1] = excl + c0;
    if (t == 1023) g_blk[b] = sc[1023];
}

// Phase B: one warp scans block sums (exclusive)
__global__ void k_scanB(int nb, int N, int E) {
    int t = threadIdx.x;
    int v = (t < nb) ? g_blk[t] : 0;
    int incl = v;
#pragma unroll
    for (int d = 1; d < 32; d <<= 1) {
        int u = __shfl_up_sync(0xffffffffu, incl, d);
        if (t >= d) incl += u;
    }
    if (t < nb) g_blkoff[t] = incl - v;
    if (t == 0) g_off[N] = E;
}

// Phase C: add block offsets, init g_cur
__global__ void k_scanC(int N) {
    int i = blockIdx.x * blockDim.x + threadIdx.x;
    if (i < N) {
        int v = g_off[i] + g_blkoff[i >> 11];
        g_off[i] = v;
        g_cur[i] = v;
    }
}

__global__ void k_perm(int E) {
    int i = blockIdx.x * blockDim.x + threadIdx.x;
    int T = gridDim.x * blockDim.x;
    for (int e = i; e < E; e += T) {
        int r = g_row[e];
        int p = atomicAdd(&g_cur[r], 1);
        g_perm[p] = e;
    }
}

// ---------------- per-node feature sum (gather, predicated unroll-8) -------
__global__ void k_agg(const float* __restrict__ x, const float* __restrict__ ea,
                      int N) {
    int lane = threadIdx.x & 31;
    int warp = (blockIdx.x * blockDim.x + threadIdx.x) >> 5;
    int nw = (gridDim.x * blockDim.x) >> 5;
    for (int n = warp; n < N; n += nw) {
        int beg = g_off[n], end = g_off[n + 1];
        float a0 = 0.f, a1 = 0.f, a2 = 0.f;
        if (beg < end) {
            int last = end - 1;
            for (int j = beg; j < end; j += 8) {
                int e[8]; float msk[8];
#pragma unroll
                for (int u = 0; u < 8; u++) {
                    int idx = j + u;
                    msk[u] = (idx < end) ? 1.f : 0.f;
                    e[u] = g_perm[(idx < end) ? idx : last];
                }
                float p[8], q[8], r[8];
#pragma unroll
                for (int u = 0; u < 8; u++) {
                    const float* fe = ea + (size_t)e[u] * 84;
                    if (lane < 4) p[u] = x[g_col[e[u]] * 4 + lane];
                    else          p[u] = __ldcs(fe + lane - 4);
                    q[u] = __ldcs(fe + 28 + lane);
                    r[u] = (lane < 24) ? __ldcs(fe + 60 + lane) : 0.f;
                }
#pragma unroll
                for (int u = 0; u < 8; u++) {
                    a0 += msk[u] * p[u];
                    a1 += msk[u] * q[u];
                    a2 += msk[u] * r[u];
                }
            }
        }
        float* so = g_S + (size_t)n * CH;
        so[lane] = a0;
        so[32 + lane] = a1;
        so[64 + lane] = (lane < 24) ? a2 : 0.f;
    }
}

// ---------------- M = sum_e f f^T via bf16 mma.sync (HMMA) -----------------
#define KB 128
#define ROWB 272
#define TILE_B (CH * ROWB)   // 26112

__device__ __forceinline__ void ldm_x4(uint32_t* r, uint32_t a) {
    asm volatile("ldmatrix.sync.aligned.m8n8.x4.shared.b16 {%0,%1,%2,%3}, [%4];"
                 : "=r"(r[0]), "=r"(r[1]), "=r"(r[2]), "=r"(r[3]) : "r"(a));
}
__device__ __forceinline__ void ldm_x2(uint32_t* r, uint32_t a) {
    asm volatile("ldmatrix.sync.aligned.m8n8.x2.shared.b16 {%0,%1}, [%2];"
                 : "=r"(r[0]), "=r"(r[1]) : "r"(a));
}
__device__ __forceinline__ void mma_bf16(float* c, const uint32_t* a, const uint32_t* b) {
    asm volatile("mma.sync.aligned.m16n8k16.row.col.f32.bf16.bf16.f32 "
                 "{%0,%1,%2,%3}, {%4,%5,%6,%7}, {%8,%9}, {%0,%1,%2,%3};"
                 : "+f"(c[0]), "+f"(c[1]), "+f"(c[2]), "+f"(c[3])
                 : "r"(a[0]), "r"(a[1]), "r"(a[2]), "r"(a[3]), "r"(b[0]), "r"(b[1]));
}

__global__ void __launch_bounds__(256, 2)
k_Mmma(const float* __restrict__ x, const float* __restrict__ ea, int E) {
    extern __shared__ __align__(16) char dsm[];   // 2 * TILE_B
    int tid = threadIdx.x;
    int lane = tid & 31, w = tid >> 5;
    int warp_m = w >> 2, warp_n = w & 3;   // 2 x 4
    int Rm = warp_m * 48;                  // 3 x 16 rows
    int Rn = warp_n * 24;                  // 3 x 8 cols

    float acc[3][3][4];
#pragma unroll
    for (int i = 0; i < 3; i++)
#pragma unroll
        for (int j = 0; j < 3; j++)
#pragma unroll
            for (int q = 0; q < 4; q++) acc[i][j][q] = 0.f;

    float s0 = 0.f, s1 = 0.f, s2 = 0.f;
    int nchunk = (E + KB - 1) / KB;
    int buf = 0;
    for (int c = blockIdx.x; c < nchunk; c += gridDim.x, buf ^= 1) {
        long long base = (long long)c * KB;
        char* tp = dsm + buf * TILE_B;
#pragma unroll
        for (int half = 0; half < 2; half++) {
            float v0[8], v1[8], v2[8];
#pragma unroll
            for (int u = 0; u < 8; u++) {
                long long e = base + w * 16 + half * 8 + u;
                v0[u] = 0.f; v1[u] = 0.f; v2[u] = 0.f;
                if (e < E) {
                    const float* fe = ea + e * 84;
                    if (lane < 4) v0[u] = x[g_col[e] * 4 + lane];
                    else          v0[u] = __ldcs(fe + lane - 4);
                    v1[u] = __ldcs(fe + 28 + lane);
                    if (lane < 24) v2[u] = __ldcs(fe + 60 + lane);
                }
            }
#pragma unroll
            for (int u = 0; u < 8; u++) {
                int ee = w * 16 + half * 8 + u;
                s0 += v0[u]; s1 += v1[u]; s2 += v2[u];
                *(__nv_bfloat16*)(tp + lane * ROWB + ee * 2) = __float2bfloat16(v0[u]);
                *(__nv_bfloat16*)(tp + (32 + lane) * ROWB + ee * 2) = __float2bfloat16(v1[u]);
                *(__nv_bfloat16*)(tp + (64 + lane) * ROWB + ee * 2) =
                    (lane < 24) ? __float2bfloat16(v2[u]) : __nv_bfloat16(0.f);
            }
        }
        __syncthreads();
        uint32_t tb = smem_u32(tp);
#pragma unroll
        for (int ks = 0; ks < KB / 16; ks++) {
            uint32_t af[3][4], bf[3][2];
#pragma unroll
            for (int i = 0; i < 3; i++) {
                uint32_t addr = tb + (uint32_t)((Rm + i * 16 + (lane & 15)) * ROWB
                                                + ks * 32 + (lane >> 4) * 16);
                ldm_x4(af[i], addr);
            }
#pragma unroll
            for (int j = 0; j < 3; j++) {
                uint32_t addr = tb + (uint32_t)((Rn + j * 8 + (lane & 7)) * ROWB
                                                + ks * 32 + ((lane >> 3) & 1) * 16);
                ldm_x2(bf[j], addr);
            }
#pragma unroll
            for (int i = 0; i < 3; i++)
#pragma unroll
                for (int j = 0; j < 3; j++) mma_bf16(acc[i][j], af[i], bf[j]);
        }
    }
#pragma unroll
    for (int i = 0; i < 3; i++)
#pragma unroll
        for (int j = 0; j < 3; j++) {
            int row = Rm + i * 16 + (lane >> 2);
            int col = Rn + j * 8 + (lane & 3) * 2;
            atomicAdd(&g_M[row * CH + col], acc[i][j][0]);
            atomicAdd(&g_M[row * CH + col + 1], acc[i][j][1]);
            atomicAdd(&g_M[(row + 8) * CH + col], acc[i][j][2]);
            atomicAdd(&g_M[(row + 8) * CH + col + 1], acc[i][j][3]);
        }
    atomicAdd(&g_sv[lane], s0);
    atomicAdd(&g_sv[32 + lane], s1);
    if (lane < 24) atomicAdd(&g_sv[64 + lane], s2);
}

// ---------------- BN stats --------------------------------------------------
__global__ void k_bn(const float* __restrict__ W1, const float* __restrict__ b1,
                     const float* __restrict__ gamma, float fE) {
    int c = blockIdx.x;
    int t = threadIdx.x;  // 96 threads
    __shared__ float w[CH];
    __shared__ float rq[CH];
    __shared__ float rs[CH];
    w[t] = (t < 88) ? W1[t * OC + c] : 0.f;
    __syncthreads();
    float q = 0.f;
    if (t < 88) {
        const float* Mr = g_M + t * CH;
        for (int k = 0; k < 88; k++) q += Mr[k] * w[k];
        q *= w[t];
    }
    rq[t] = q;
    rs[t] = (t < 88) ? g_sv[t] * w[t] : 0.f;
    __syncthreads();
    if (t == 0) {
        float Q = 0.f, SW = 0.f;
        for (int i = 0; i < 88; i++) { Q += rq[i]; SW += rs[i]; }
        float b = b1[c];
        float mean = SW / fE + b;
        float ex2 = (Q + 2.f * b * SW) / fE + b * b;
        float var = ex2 - mean * mean;
        g_mean[c] = mean;
        g_scale[c] = gamma[c] * rsqrtf(var + EPSV);
    }
}

// ---------------- node output, 4 nodes per warp iteration -------------------
__global__ void k_out(const float* __restrict__ x, const float* __restrict__ W1,
                      const float* __restrict__ b1, const float* __restrict__ beta,
                      const float* __restrict__ W2, const float* __restrict__ b2,
                      float* __restrict__ out, int N) {
    extern __shared__ float sm[];
    float* W1s = sm;             // 88*128
    float* W2s = sm + 88 * OC;   // 132*64
    int tid = threadIdx.x;
    for (int i = tid; i < 88 * OC; i += blockDim.x) W1s[i] = W1[i];
    for (int i = tid; i < 132 * OUTC; i += blockDim.x) W2s[i] = W2[i];
    __syncthreads();
    int lane = tid & 31;
    int warp = (blockIdx.x * blockDim.x + tid) >> 5;
    int nw = (gridDim.x * blockDim.x) >> 5;
    float mn0 = g_mean[lane], mn1 = g_mean[32 + lane], mn2 = g_mean[64 + lane], mn3 = g_mean[96 + lane];
    float sc0 = g_scale[lane], sc1 = g_scale[32 + lane], sc2 = g_scale[64 + lane], sc3 = g_scale[96 + lane];
    float bt0 = beta[lane], bt1 = beta[32 + lane], bt2 = beta[64 + lane], bt3 = beta[96 + lane];
    float bo0 = b1[lane], bo1 = b1[32 + lane], bo2 = b1[64 + lane], bo3 = b1[96 + lane];
    float bb0 = b2[lane], bb1 = b2[32 + lane];

    for (int n0 = warp * 4; n0 < N; n0 += nw * 4) {
        float sr0[4], sr1[4], sr2[4], rcp[4], tv[4];
#pragma unroll
        for (int m = 0; m < 4; m++) {
            int n = n0 + m;
            if (n < N) {
                const float* so = g_S + (size_t)n * CH;
                sr0[m] = so[lane]; sr1[m] = so[32 + lane]; sr2[m] = so[64 + lane];
                int cnt = g_off[n + 1] - g_off[n];
                tv[m] = (cnt > 0) ? 1.f : 0.f;
                rcp[m] = (cnt > 0) ? 1.f / (float)cnt : 0.f;
            } else { sr0[m] = sr1[m] = sr2[m] = 0.f; tv[m] = 0.f; rcp[m] = 0.f; }
        }
        float a0[4] = {0,0,0,0}, a1[4] = {0,0,0,0}, a2[4] = {0,0,0,0}, a3[4] = {0,0,0,0};
#pragma unroll
        for (int cc = 0; cc < 32; cc++) {
            const float* wr = W1s + cc * OC + lane;
            float w0 = wr[0], w1 = wr[32], w2 = wr[64], w3 = wr[96];
#pragma unroll
            for (int m = 0; m < 4; m++) {
                float v = __shfl_sync(0xffffffffu, sr0[m], cc);
                a0[m] += v * w0; a1[m] += v * w1; a2[m] += v * w2; a3[m] += v * w3;
            }
        }
#pragma unroll
        for (int cc = 0; cc < 32; cc++) {
            const float* wr = W1s + (32 + cc) * OC + lane;
            float w0 = wr[0], w1 = wr[32], w2 = wr[64], w3 = wr[96];
#pragma unroll
            for (int m = 0; m < 4; m++) {
                float v = __shfl_sync(0xffffffffu, sr1[m], cc);
                a0[m] += v * w0; a1[m] += v * w1; a2[m] += v * w2; a3[m] += v * w3;
            }
        }
#pragma unroll
        for (int cc = 0; cc < 24; cc++) {
            const float* wr = W1s + (64 + cc) * OC + lane;
            float w0 = wr[0], w1 = wr[32], w2 = wr[64], w3 = wr[96];
#pragma unroll
            for (int m = 0; m < 4; m++) {
                float v = __shfl_sync(0xffffffffu, sr2[m], cc);
                a0[m] += v * w0; a1[m] += v * w1; a2[m] += v * w2; a3[m] += v * w3;
            }
        }
        float ag0[4], ag1[4], ag2[4], ag3[4];
#pragma unroll
        for (int m = 0; m < 4; m++) {
            ag0[m] = ((a0[m] * rcp[m] + bo0 - mn0) * sc0 + bt0) * tv[m];
            ag1[m] = ((a1[m] * rcp[m] + bo1 - mn1) * sc1 + bt1) * tv[m];
            ag2[m] = ((a2[m] * rcp[m] + bo2 - mn2) * sc2 + bt2) * tv[m];
            ag3[m] = ((a3[m] * rcp[m] + bo3 - mn3) * sc3 + bt3) * tv[m];
        }
        float o0[4], o1[4];
#pragma unroll
        for (int m = 0; m < 4; m++) { o0[m] = bb0; o1[m] = bb1; }
#pragma unroll
        for (int k = 0; k < 4; k++) {
            float wa = W2s[k * OUTC + lane], wb = W2s[k * OUTC + 32 + lane];
#pragma unroll
            for (int m = 0; m < 4; m++) {
                int n = n0 + m;
                float xv = (n < N) ? x[(size_t)n * 4 + k] : 0.f;
                o0[m] += xv * wa; o1[m] += xv * wb;
            }
        }
#pragma unroll
        for (int cc = 0; cc < 32; cc++) {
            const float* wr = W2s + (4 + cc) * OUTC + lane;
            float w0 = wr[0], w1 = wr[32];
#pragma unroll
            for (int m = 0; m < 4; m++) {
                float av = __shfl_sync(0xffffffffu, ag0[m], cc);
                o0[m] += av * w0; o1[m] += av * w1;
            }
        }
#pragma unroll
        for (int cc = 0; cc < 32; cc++) {
            const float* wr = W2s + (36 + cc) * OUTC + lane;
            float w0 = wr[0], w1 = wr[32];
#pragma unroll
            for (int m = 0; m < 4; m++) {
                float av = __shfl_sync(0xffffffffu, ag1[m], cc);
                o0[m] += av * w0; o1[m] += av * w1;
            }
        }
#pragma unroll
        for (int cc = 0; cc < 32; cc++) {
            const float* wr = W2s + (68 + cc) * OUTC + lane;
            float w0 = wr[0], w1 = wr[32];
#pragma unroll
            for (int m = 0; m < 4; m++) {
                float av = __shfl_sync(0xffffffffu, ag2[m], cc);
                o0[m] += av * w0; o1[m] += av * w1;
            }
        }
#pragma unroll
        for (int cc = 0; cc < 32; cc++) {
            const float* wr = W2s + (100 + cc) * OUTC + lane;
            float w0 = wr[0], w1 = wr[32];
#pragma unroll
            for (int m = 0; m < 4; m++) {
                float av = __shfl_sync(0xffffffffu, ag3[m], cc);
                o0[m] += av * w0; o1[m] += av * w1;
            }
        }
#pragma unroll
        for (int m = 0; m < 4; m++) {
            int n = n0 + m;
            if (n < N) {
                out[(size_t)n * 64 + lane] = fmaxf(o0[m], 0.f);
                out[(size_t)n * 64 + 32 + lane] = fmaxf(o1[m], 0.f);
            }
        }
    }
}

// ---------------- launcher --------------------------------------------------
extern "C" void kernel_launch(void* const* d_in, const int* in_sizes, int n_in,
                              void* d_out, int out_size) {
    const float* x     = (const float*)d_in[0];
    const void*  ei    = d_in[1];
    const float* ea    = (const float*)d_in[2];
    const float* W1    = (const float*)d_in[3];
    const float* b1    = (const float*)d_in[4];
    const float* gamma = (const float*)d_in[5];
    const float* beta  = (const float*)d_in[6];
    const float* W2    = (const float*)d_in[7];
    const float* b2    = (const float*)d_in[8];
    float* out = (float*)d_out;
    int N = in_sizes[0] / 4;
    int E = in_sizes[2] / 84;
    int nb = (N + SCAN_CH - 1) / SCAN_CH;

    k_detect<<<1, 32>>>(ei);
    k_zero<<<128, 256>>>(N);
    k_convhist<<<512, 256>>>(ei, E);

    // fork: k_Mmma depends only on g_col + zeroed g_M/g_sv
    cudaEventRecord(g_hx.evFork, 0);
    cudaStreamWaitEvent(g_hx.s1, g_hx.evFork, 0);
    const int msmem = 2 * TILE_B;   // 52224 B
    cudaFuncSetAttribute(k_Mmma, cudaFuncAttributeMaxDynamicSharedMemorySize, msmem);
    k_Mmma<<<296, 256, msmem, g_hx.s1>>>(x, ea, E);
    cudaEventRecord(g_hx.evJoin, g_hx.s1);

    // main chain: scan -> perm -> agg
    k_scanA<<<nb, 1024>>>(N);
    k_scanB<<<1, 32>>>(nb, N, E);
    k_scanC<<<(N + 255) / 256, 256>>>(N);
    k_perm<<<512, 256>>>(E);
    k_agg<<<1184, 256>>>(x, ea, N);

    // join: bn needs g_M/g_sv from k_Mmma
    cudaStreamWaitEvent(0, g_hx.evJoin, 0);
    k_bn<<<128, 96>>>(W1, b1, gamma, (float)E);
    const int smem = (88 * OC + 132 * OUTC) * 4;  // 78848 B
    cudaFuncSetAttribute(k_out, cudaFuncAttributeMaxDynamicSharedMemorySize, smem);
    k_out<<<296, 256, smem>>>(x, W1, b1, beta, W2, b2, out, N);
}